// round 7
// baseline (speedup 1.0000x reference)
#include <cuda_runtime.h>
#include <cuda_bf16.h>
#include <cstdint>

#define B_ 8
#define T_ 1024
#define D_ 1024
#define H_ 16
#define HD 64
#define M_ (B_ * T_)     // 8192
#define NELT (M_ * D_)   // 8388608
#define K3 3072          // bf16x3 concat K (O-GEMM)
#define NIT (K3 / 64)    // 48
#define K4I 4096         // int8 digit concat K (QKV GEMM)
#define NITI (K4I / 128) // 32

// quantization: x15 = round(x*S) in [-11520, 11520]; digits a(7b-ish), b in [-64,63]
#define QMAX 11520
#define SX 1920.0f       // 11520 / 6.0
#define SW 92160.0f      // 11520 / 0.125

// ---------------- scratch (static __device__; no cudaMalloc allowed) --------
__device__ __align__(256) int8_t g_xi[(size_t)M_ * K4I];        // [a|b|a|b]
__device__ __align__(256) int8_t g_wi[(size_t)3 * D_ * K4I];    // [c|c|d|d], rows q;k;v

__device__ __align__(256) __nv_bfloat16 g_qh[NELT];
__device__ __align__(256) __nv_bfloat16 g_ql[NELT];
__device__ __align__(256) __nv_bfloat16 g_kh[NELT];
__device__ __align__(256) __nv_bfloat16 g_kl[NELT];
__device__ __align__(256) __nv_bfloat16 g_vh[NELT];
__device__ __align__(256) __nv_bfloat16 g_vl[NELT];
__device__ __align__(256) __nv_bfloat16 g_vth[NELT];
__device__ __align__(256) __nv_bfloat16 g_vtl[NELT];

__device__ __align__(256) __nv_bfloat16 g_a3[(size_t)M_ * K3]; // attn out [hi|lo|hi]
__device__ __align__(256) __nv_bfloat16 g_wo3[(size_t)D_ * K3];

// ---------------- helpers ---------------------------------------------------
__device__ __forceinline__ uint32_t smem_u32(const void* p) {
    uint32_t a;
    asm("{ .reg .u64 t; cvta.to.shared.u64 t, %1; cvt.u32.u64 %0, t; }" : "=r"(a) : "l"(p));
    return a;
}
__device__ __forceinline__ uint32_t swz(uint32_t off) { return off ^ ((off >> 3) & 0x70); }

#define CP_ASYNC16(dst, src) \
    asm volatile("cp.async.cg.shared.global [%0], [%1], 16;" :: "r"(dst), "l"(src))
#define CP_COMMIT()  asm volatile("cp.async.commit_group;" ::: "memory")
#define CP_WAIT1()   asm volatile("cp.async.wait_group 1;" ::: "memory")

#define LDSM_X4(r0, r1, r2, r3, addr) \
    asm volatile("ldmatrix.sync.aligned.m8n8.x4.shared.b16 {%0,%1,%2,%3}, [%4];" \
        : "=r"(r0), "=r"(r1), "=r"(r2), "=r"(r3) : "r"(addr))

#define MMA_BF16(c0, c1, c2, c3, a0, a1, a2, a3, b0, b1) \
    asm volatile("mma.sync.aligned.m16n8k16.row.col.f32.bf16.bf16.f32 " \
        "{%0,%1,%2,%3}, {%4,%5,%6,%7}, {%8,%9}, {%0,%1,%2,%3};" \
        : "+f"(c0), "+f"(c1), "+f"(c2), "+f"(c3) \
        : "r"(a0), "r"(a1), "r"(a2), "r"(a3), "r"(b0), "r"(b1))

#define MMA_S8(c0, c1, c2, c3, a0, a1, a2, a3, b0, b1) \
    asm volatile("mma.sync.aligned.m16n8k32.row.col.s32.s8.s8.s32 " \
        "{%0,%1,%2,%3}, {%4,%5,%6,%7}, {%8,%9}, {%0,%1,%2,%3};" \
        : "+r"(c0), "+r"(c1), "+r"(c2), "+r"(c3) \
        : "r"(a0), "r"(a1), "r"(a2), "r"(a3), "r"(b0), "r"(b1))

__device__ __forceinline__ uint32_t packbf(float lo, float hi) {
    uint32_t r;
    asm("cvt.rn.bf16x2.f32 %0, %1, %2;" : "=r"(r) : "f"(hi), "f"(lo));
    return r;
}
__device__ __forceinline__ float bflo(uint32_t u) { return __int_as_float(u << 16); }
__device__ __forceinline__ float bfhi(uint32_t u) { return __int_as_float(u & 0xFFFF0000u); }

__device__ __forceinline__ float fexp2(float y) {
    y = fmaxf(y, -126.0f);
    float t = y + 12582912.0f;
    int i = __float_as_int(t) - 0x4B400000;
    float f = y - (t - 12582912.0f);
    float p = 0.001333356f;
    p = fmaf(p, f, 0.009618129f);
    p = fmaf(p, f, 0.05550411f);
    p = fmaf(p, f, 0.2402265f);
    p = fmaf(p, f, 0.6931472f);
    p = fmaf(p, f, 1.0f);
    return p * __int_as_float((i + 127) << 23);
}

// ---------------- fp32 -> int8 digit pairs, K-concat4 layout -----------------
// modeA: [a|b|a|b]   modeB: [c|c|d|d]
__global__ void quanti8(const float* __restrict__ s, int8_t* __restrict__ d,
                        int n4, float S, int modeB) {
    int i = blockIdx.x * blockDim.x + threadIdx.x;
    if (i >= n4) return;
    float4 v = ((const float4*)s)[i];
    int x0 = max(-QMAX, min(QMAX, __float2int_rn(v.x * S)));
    int x1 = max(-QMAX, min(QMAX, __float2int_rn(v.y * S)));
    int x2 = max(-QMAX, min(QMAX, __float2int_rn(v.z * S)));
    int x3 = max(-QMAX, min(QMAX, __float2int_rn(v.w * S)));
    int a0 = (x0 + 64) >> 7, a1 = (x1 + 64) >> 7, a2 = (x2 + 64) >> 7, a3 = (x3 + 64) >> 7;
    char4 av = make_char4((char)a0, (char)a1, (char)a2, (char)a3);
    char4 bv = make_char4((char)(x0 - (a0 << 7)), (char)(x1 - (a1 << 7)),
                          (char)(x2 - (a2 << 7)), (char)(x3 - (a3 << 7)));
    int e = 4 * i;
    int row = e >> 10;
    int col = e & 1023;
    char4* base = (char4*)(d + ((size_t)row << 12) + col);
    if (modeB) { base[0] = av; base[256] = av; base[512] = bv; base[768] = bv; }
    else       { base[0] = av; base[256] = bv; base[512] = av; base[768] = bv; }
}

// ---------------- fp32 -> bf16 hi/lo split into K-concat3 (B layout) ---------
__global__ void split3w(const float* __restrict__ s, __nv_bfloat16* __restrict__ d, int n2) {
    int i = blockIdx.x * blockDim.x + threadIdx.x;
    if (i >= n2) return;
    float2 v = ((const float2*)s)[i];
    __nv_bfloat16 h0 = __float2bfloat16_rn(v.x);
    __nv_bfloat16 h1 = __float2bfloat16_rn(v.y);
    __nv_bfloat16 l0 = __float2bfloat16_rn(v.x - __bfloat162float(h0));
    __nv_bfloat16 l1 = __float2bfloat16_rn(v.y - __bfloat162float(h1));
    __nv_bfloat162 hp = __halves2bfloat162(h0, h1);
    __nv_bfloat162 lp = __halves2bfloat162(l0, l1);
    int e = 2 * i;
    int row = e >> 10;
    int col = e & 1023;
    __nv_bfloat162* base = (__nv_bfloat162*)(d + (size_t)row * K3 + col);
    base[0] = hp; base[512] = hp; base[1024] = lp;   // [hi | hi | lo]
}

// ---------------- int8 IMMA fused QKV GEMM -----------------------------------
// C[M,3072] = exact15(x) @ exact15(Wqkv)^T via digit GEMM, K-concat4.
// 128 threads, 4 warps 64x64, BK=128 int8, 3-stage cp.async, 2 CTA/SM.
#define STAGE_I 32768
#define SM_GI (3 * STAGE_I)

__global__ __launch_bounds__(128, 2)
void gemm_i8_qkv(const int8_t* __restrict__ A2, const int8_t* __restrict__ B2,
                 const float* __restrict__ bq, const float* __restrict__ bvv,
                 __nv_bfloat16* __restrict__ qh, __nv_bfloat16* __restrict__ ql,
                 __nv_bfloat16* __restrict__ kh, __nv_bfloat16* __restrict__ kl,
                 __nv_bfloat16* __restrict__ vh, __nv_bfloat16* __restrict__ vl) {
    extern __shared__ char smem[];
    const uint32_t sbase = smem_u32(smem);
    const int tid = threadIdx.x;
    const int wid = tid >> 5;
    const int lane = tid & 31;
    const int m0 = blockIdx.y * 128;
    const int n0 = blockIdx.x * 128;

    const int r_ld = tid >> 3;
    const int c_ld = tid & 7;

    const int8_t* Abase = A2 + ((size_t)(m0 + r_ld * 8) << 12) + c_ld * 16;
    const int8_t* Bbase = B2 + ((size_t)(n0 + r_ld * 8) << 12) + c_ld * 16;

    int acc[4][8][4];
#pragma unroll
    for (int i = 0; i < 4; i++)
#pragma unroll
        for (int j = 0; j < 8; j++)
#pragma unroll
            for (int t = 0; t < 4; t++) acc[i][j][t] = 0;

    auto load_stage = [&](int stage, int kt) {
        const uint32_t sA = sbase + stage * STAGE_I;
        const uint32_t sB = sA + 16384;
        const size_t koff = (size_t)kt * 128;
#pragma unroll
        for (int j = 0; j < 8; j++) {
            const int r = r_ld * 8 + j;
            CP_ASYNC16(sA + swz((uint32_t)(r * 128 + c_ld * 16)),
                       Abase + ((size_t)j << 12) + koff);
        }
#pragma unroll
        for (int j = 0; j < 8; j++) {
            const int r = r_ld * 8 + j;
            CP_ASYNC16(sB + swz((uint32_t)(r * 128 + c_ld * 16)),
                       Bbase + ((size_t)j << 12) + koff);
        }
    };

    load_stage(0, 0); CP_COMMIT();
    load_stage(1, 1); CP_COMMIT();

    const int wm = (wid & 1) * 64;
    const int wn = (wid >> 1) * 64;
    const int lrow = lane & 15;
    const int lkhalf = ((lane >> 4) & 1) * 16;

    for (int kt = 0; kt < NITI; kt++) {
        CP_WAIT1();
        __syncthreads();
        if (kt + 2 < NITI) load_stage((kt + 2) % 3, kt + 2);
        CP_COMMIT();

        const uint32_t sA = sbase + (kt % 3) * STAGE_I;
        const uint32_t sB = sA + 16384;

#pragma unroll
        for (int ks = 0; ks < 4; ks++) {           // 4 x k32 slices per 128B
            const uint32_t kb = ks * 32 + lkhalf;
            uint32_t a[4][4], b[8][2];
#pragma unroll
            for (int mt = 0; mt < 4; mt++) {
                const uint32_t ad = sA + swz((uint32_t)((wm + mt * 16 + lrow) * 128) + kb);
                LDSM_X4(a[mt][0], a[mt][1], a[mt][2], a[mt][3], ad);
            }
#pragma unroll
            for (int np = 0; np < 4; np++) {
                const uint32_t bd = sB + swz((uint32_t)((wn + np * 16 + lrow) * 128) + kb);
                LDSM_X4(b[2 * np][0], b[2 * np + 1][0], b[2 * np][1], b[2 * np + 1][1], bd);
            }
#pragma unroll
            for (int mt = 0; mt < 4; mt++)
#pragma unroll
                for (int nt = 0; nt < 8; nt++)
                    MMA_S8(acc[mt][nt][0], acc[mt][nt][1], acc[mt][nt][2], acc[mt][nt][3],
                           (uint32_t)a[mt][0], (uint32_t)a[mt][1],
                           (uint32_t)a[mt][2], (uint32_t)a[mt][3],
                           (uint32_t)b[nt][0], (uint32_t)b[nt][1]);
        }

        // digit-weight rescale points: after region ac (kt 7) and after ad (kt 23)
        if (kt == 7 || kt == 23) {
#pragma unroll
            for (int i = 0; i < 4; i++)
#pragma unroll
                for (int j = 0; j < 8; j++)
#pragma unroll
                    for (int t = 0; t < 4; t++) acc[i][j][t] <<= 7;
        }
    }

    // ---- epilogue: acc -> fp32 -> bf16 hi/lo, + bias per region ----
    const float invS = 1.0f / (SX * SW);
    const int em = m0 + wm + (lane >> 2);
    const int region = n0 >> 10;
    const int nbase = (n0 & 1023) + wn + (lane & 3) * 2;
    const float* bias = (region == 0 ? bq : (region == 2 ? bvv : nullptr));
    __nv_bfloat16* Dhi = (region == 0 ? qh : (region == 1 ? kh : vh));
    __nv_bfloat16* Dlo = (region == 0 ? ql : (region == 1 ? kl : vl));

#pragma unroll
    for (int mt = 0; mt < 4; mt++) {
#pragma unroll
        for (int nt = 0; nt < 8; nt++) {
            const int n = nbase + nt * 8;
            float2 bb = make_float2(0.f, 0.f);
            if (bias) bb = *(const float2*)(bias + n);
            float v0 = (float)acc[mt][nt][0] * invS + bb.x;
            float v1 = (float)acc[mt][nt][1] * invS + bb.y;
            float v2 = (float)acc[mt][nt][2] * invS + bb.x;
            float v3 = (float)acc[mt][nt][3] * invS + bb.y;
            const size_t r0 = (size_t)(em + mt * 16) * D_ + n;
            const size_t r1 = (size_t)(em + mt * 16 + 8) * D_ + n;
            uint32_t h0 = packbf(v0, v1), h1 = packbf(v2, v3);
            *(uint32_t*)(Dhi + r0) = h0;
            *(uint32_t*)(Dhi + r1) = h1;
            *(uint32_t*)(Dlo + r0) = packbf(v0 - bflo(h0), v1 - bfhi(h0));
            *(uint32_t*)(Dlo + r1) = packbf(v2 - bflo(h1), v3 - bfhi(h1));
        }
    }
}

// ---------------- bf16x3 O-projection GEMM (unchanged from R5) ---------------
#define STAGE_B 32768
#define SM_GEMM (3 * STAGE_B)

__global__ __launch_bounds__(128, 2)
void gemm_o(const __nv_bfloat16* __restrict__ A2, const __nv_bfloat16* __restrict__ B2,
            const float* __restrict__ bo, float* __restrict__ C) {
    extern __shared__ char smem[];
    const uint32_t sbase = smem_u32(smem);
    const int tid = threadIdx.x;
    const int wid = tid >> 5;
    const int lane = tid & 31;
    const int m0 = blockIdx.y * 128;
    const int n0 = blockIdx.x * 128;

    const int r_ld = tid >> 3;
    const int c_ld = tid & 7;

    const __nv_bfloat16* Abase = A2 + (size_t)(m0 + r_ld * 8) * K3 + c_ld * 8;
    const __nv_bfloat16* Bbase = B2 + (size_t)(n0 + r_ld * 8) * K3 + c_ld * 8;

    float acc[4][8][4];
#pragma unroll
    for (int i = 0; i < 4; i++)
#pragma unroll
        for (int j = 0; j < 8; j++)
#pragma unroll
            for (int t = 0; t < 4; t++) acc[i][j][t] = 0.0f;

    auto load_stage = [&](int stage, int kt) {
        const uint32_t sA = sbase + stage * STAGE_B;
        const uint32_t sB = sA + 16384;
        const size_t koff = (size_t)kt * 64;
#pragma unroll
        for (int j = 0; j < 8; j++) {
            const int r = r_ld * 8 + j;
            CP_ASYNC16(sA + swz((uint32_t)(r * 128 + c_ld * 16)),
                       Abase + (size_t)j * K3 + koff);
        }
#pragma unroll
        for (int j = 0; j < 8; j++) {
            const int r = r_ld * 8 + j;
            CP_ASYNC16(sB + swz((uint32_t)(r * 128 + c_ld * 16)),
                       Bbase + (size_t)j * K3 + koff);
        }
    };

    load_stage(0, 0); CP_COMMIT();
    load_stage(1, 1); CP_COMMIT();

    const int wm = (wid & 1) * 64;
    const int wn = (wid >> 1) * 64;
    const int lrow = lane & 15;
    const int lkhalf = ((lane >> 4) & 1) * 16;

    for (int kt = 0; kt < NIT; kt++) {
        CP_WAIT1();
        __syncthreads();
        if (kt + 2 < NIT) load_stage((kt + 2) % 3, kt + 2);
        CP_COMMIT();

        const uint32_t sA = sbase + (kt % 3) * STAGE_B;
        const uint32_t sB = sA + 16384;

#pragma unroll
        for (int k16 = 0; k16 < 4; k16++) {
            const uint32_t kb = k16 * 32 + lkhalf;
            uint32_t a[4][4], b[8][2];
#pragma unroll
            for (int mt = 0; mt < 4; mt++) {
                const uint32_t ad = sA + swz((uint32_t)((wm + mt * 16 + lrow) * 128) + kb);
                LDSM_X4(a[mt][0], a[mt][1], a[mt][2], a[mt][3], ad);
            }
#pragma unroll
            for (int np = 0; np < 4; np++) {
                const uint32_t bd = sB + swz((uint32_t)((wn + np * 16 + lrow) * 128) + kb);
                LDSM_X4(b[2 * np][0], b[2 * np + 1][0], b[2 * np][1], b[2 * np + 1][1], bd);
            }
#pragma unroll
            for (int mt = 0; mt < 4; mt++)
#pragma unroll
                for (int nt = 0; nt < 8; nt++)
                    MMA_BF16(acc[mt][nt][0], acc[mt][nt][1], acc[mt][nt][2], acc[mt][nt][3],
                             a[mt][0], a[mt][1], a[mt][2], a[mt][3],
                             b[nt][0], b[nt][1]);
        }
    }

    const int em = m0 + wm + (lane >> 2);
    const int en = n0 + wn + (lane & 3) * 2;
#pragma unroll
    for (int mt = 0; mt < 4; mt++) {
#pragma unroll
        for (int nt = 0; nt < 8; nt++) {
            const int n = en + nt * 8;
            float2 bb = *(const float2*)(bo + n);
            *(float2*)(C + (size_t)(em + mt * 16) * D_ + n) =
                make_float2(acc[mt][nt][0] + bb.x, acc[mt][nt][1] + bb.y);
            *(float2*)(C + (size_t)(em + mt * 16 + 8) * D_ + n) =
                make_float2(acc[mt][nt][2] + bb.x, acc[mt][nt][3] + bb.y);
        }
    }
}

// ---------------- V transpose ------------------------------------------------
__global__ __launch_bounds__(128, 4)
void transp_v(const __nv_bfloat16* __restrict__ vh, const __nv_bfloat16* __restrict__ vl,
              __nv_bfloat16* __restrict__ vth, __nv_bfloat16* __restrict__ vtl) {
    __shared__ __nv_bfloat16 s[64][72];
    const int tid = threadIdx.x;
    const int tt = blockIdx.x, h = blockIdx.y, b = blockIdx.z;
    const __nv_bfloat16* src[2] = {vh, vl};
    __nv_bfloat16* dst[2] = {vth, vtl};
#pragma unroll
    for (int m = 0; m < 2; m++) {
        __syncthreads();
#pragma unroll
        for (int it = 0; it < 4; it++) {
            const int idx = it * 128 + tid;
            const int r = idx >> 3, c8 = idx & 7;
            *(uint4*)&s[r][c8 * 8] =
                *(const uint4*)(src[m] + (size_t)(b * T_ + tt * 64 + r) * D_ + h * 64 + c8 * 8);
        }
        __syncthreads();
#pragma unroll
        for (int it = 0; it < 4; it++) {
            const int idx = it * 128 + tid;
            const int d = idx >> 3, t8 = idx & 7;
            __nv_bfloat16 tmp[8];
#pragma unroll
            for (int j = 0; j < 8; j++) tmp[j] = s[t8 * 8 + j][d];
            *(uint4*)(dst[m] + (size_t)((b * H_ + h) * 64 + d) * T_ + tt * 64 + t8 * 8) =
                *(uint4*)tmp;
        }
    }
}

// ---------------- tensor-core causal flash attention -------------------------
// epilogue now writes a3 [hi|lo|hi] bf16 K-concat3 directly.
#define AT_SQ    32768
#define AT_STAGE 32768
#define AT_SMEM  (AT_SQ + 3 * AT_STAGE)

__global__ __launch_bounds__(256, 1)
void attn_mma(const __nv_bfloat16* __restrict__ qh_, const __nv_bfloat16* __restrict__ ql_,
              const __nv_bfloat16* __restrict__ kh_, const __nv_bfloat16* __restrict__ kl_,
              const __nv_bfloat16* __restrict__ vth_, const __nv_bfloat16* __restrict__ vtl_,
              __nv_bfloat16* __restrict__ a3) {
    extern __shared__ char smem[];
    const uint32_t sbase = smem_u32(smem);
    const int tid = threadIdx.x;
    const int wid = tid >> 5;
    const int lane = tid & 31;
    const int iq = blockIdx.x;
    const int h  = blockIdx.y;
    const int b  = blockIdx.z;
    const int nblocks = 2 * iq + 2;

    {
        const __nv_bfloat16* qs[2] = {qh_, ql_};
#pragma unroll
        for (int m = 0; m < 2; m++)
#pragma unroll
            for (int it = 0; it < 4; it++) {
                const int idx = it * 256 + tid;
                const int r = idx >> 3, c = idx & 7;
                CP_ASYNC16(sbase + m * 16384 + swz((uint32_t)(r * 128 + c * 16)),
                           qs[m] + (size_t)(b * T_ + iq * 128 + r) * D_ + h * 64 + c * 8);
            }
    }
    auto pf_kv = [&](int jb) {
        const uint32_t s0 = sbase + AT_SQ + (jb % 3) * AT_STAGE;
        const __nv_bfloat16* ks[2] = {kh_, kl_};
        const __nv_bfloat16* vs[2] = {vth_, vtl_};
#pragma unroll
        for (int m = 0; m < 2; m++)
#pragma unroll
            for (int it = 0; it < 2; it++) {
                const int idx = it * 256 + tid;
                const int r = idx >> 3, c = idx & 7;
                CP_ASYNC16(s0 + m * 8192 + swz((uint32_t)(r * 128 + c * 16)),
                           ks[m] + (size_t)(b * T_ + jb * 64 + r) * D_ + h * 64 + c * 8);
            }
#pragma unroll
        for (int m = 0; m < 2; m++)
#pragma unroll
            for (int it = 0; it < 2; it++) {
                const int idx = it * 256 + tid;
                const int r = idx >> 3, c = idx & 7;
                CP_ASYNC16(s0 + 16384 + m * 8192 + swz((uint32_t)(r * 128 + c * 16)),
                           vs[m] + (size_t)((b * H_ + h) * 64 + r) * T_ + jb * 64 + c * 8);
            }
    };

    pf_kv(0); CP_COMMIT();
    if (nblocks > 1) pf_kv(1);
    CP_COMMIT();

    float oacc[8][4];
#pragma unroll
    for (int i = 0; i < 8; i++)
#pragma unroll
        for (int j = 0; j < 4; j++) oacc[i][j] = 0.0f;
    float l0 = 0.0f, l1 = 0.0f;

    const int m0w = iq * 128 + wid * 16;
    const int r0 = lane >> 2;
    const int c0 = (lane & 3) * 2;
    const int lrow = lane & 15;
    const int lkh = ((lane >> 4) & 1) * 16;

    for (int jb = 0; jb < nblocks; jb++) {
        CP_WAIT1();
        __syncthreads();
        if (jb + 2 < nblocks) pf_kv(jb + 2);
        CP_COMMIT();

        const uint32_t sK = sbase + AT_SQ + (jb % 3) * AT_STAGE;
        const uint32_t sV = sK + 16384;

        if (jb * 64 <= m0w + 15) {
            float sfr[8][4];
#pragma unroll
            for (int i = 0; i < 8; i++)
#pragma unroll
                for (int j = 0; j < 4; j++) sfr[i][j] = 0.0f;

#pragma unroll
            for (int k16 = 0; k16 < 4; k16++) {
                const uint32_t kb = k16 * 32 + lkh;
                uint32_t ah[4], al[4], bh[8][2], bl[8][2];
                LDSM_X4(ah[0], ah[1], ah[2], ah[3],
                        sbase + swz((uint32_t)((wid * 16 + lrow) * 128) + kb));
                LDSM_X4(al[0], al[1], al[2], al[3],
                        sbase + 16384 + swz((uint32_t)((wid * 16 + lrow) * 128) + kb));
#pragma unroll
                for (int np = 0; np < 4; np++) {
                    const uint32_t off = swz((uint32_t)((np * 16 + lrow) * 128) + kb);
                    LDSM_X4(bh[2 * np][0], bh[2 * np + 1][0], bh[2 * np][1], bh[2 * np + 1][1],
                            sK + off);
                    LDSM_X4(bl[2 * np][0], bl[2 * np + 1][0], bl[2 * np][1], bl[2 * np + 1][1],
                            sK + 8192 + off);
                }
#pragma unroll
                for (int nt = 0; nt < 8; nt++) {
                    MMA_BF16(sfr[nt][0], sfr[nt][1], sfr[nt][2], sfr[nt][3],
                             ah[0], ah[1], ah[2], ah[3], bh[nt][0], bh[nt][1]);
                    MMA_BF16(sfr[nt][0], sfr[nt][1], sfr[nt][2], sfr[nt][3],
                             al[0], al[1], al[2], al[3], bh[nt][0], bh[nt][1]);
                    MMA_BF16(sfr[nt][0], sfr[nt][1], sfr[nt][2], sfr[nt][3],
                             ah[0], ah[1], ah[2], ah[3], bl[nt][0], bl[nt][1]);
                }
            }

            const bool needmask = (jb * 64 + 63 > m0w);
#pragma unroll
            for (int nt = 0; nt < 8; nt++) {
#pragma unroll
                for (int e = 0; e < 4; e++) {
                    const int col_g = jb * 64 + nt * 8 + c0 + (e & 1);
                    const int row_g = m0w + r0 + ((e >> 1) << 3);
                    float p = fexp2(sfr[nt][e] * 0.1803368801f);
                    if (needmask && col_g > row_g) p = 0.0f;
                    sfr[nt][e] = p;
                    if (e < 2) l0 += p; else l1 += p;
                }
            }

            uint32_t pah[4][4], pal[4][4];
#pragma unroll
            for (int kk = 0; kk < 4; kk++) {
                const float* t0 = sfr[2 * kk];
                const float* t1 = sfr[2 * kk + 1];
                pah[kk][0] = packbf(t0[0], t0[1]);
                pah[kk][1] = packbf(t0[2], t0[3]);
                pah[kk][2] = packbf(t1[0], t1[1]);
                pah[kk][3] = packbf(t1[2], t1[3]);
                pal[kk][0] = packbf(t0[0] - bflo(pah[kk][0]), t0[1] - bfhi(pah[kk][0]));
                pal[kk][1] = packbf(t0[2] - bflo(pah[kk][1]), t0[3] - bfhi(pah[kk][1]));
                pal[kk][2] = packbf(t1[0] - bflo(pah[kk][2]), t1[1] - bfhi(pah[kk][2]));
                pal[kk][3] = packbf(t1[2] - bflo(pah[kk][3]), t1[3] - bfhi(pah[kk][3]));
            }

#pragma unroll
            for (int kk = 0; kk < 4; kk++) {
                const uint32_t kb = kk * 32 + lkh;
                uint32_t bvh[8][2], bvl[8][2];
#pragma unroll
                for (int np = 0; np < 4; np++) {
                    const uint32_t off = swz((uint32_t)((np * 16 + lrow) * 128) + kb);
                    LDSM_X4(bvh[2 * np][0], bvh[2 * np + 1][0], bvh[2 * np][1], bvh[2 * np + 1][1],
                            sV + off);
                    LDSM_X4(bvl[2 * np][0], bvl[2 * np + 1][0], bvl[2 * np][1], bvl[2 * np + 1][1],
                            sV + 8192 + off);
                }
#pragma unroll
                for (int nt = 0; nt < 8; nt++) {
                    MMA_BF16(oacc[nt][0], oacc[nt][1], oacc[nt][2], oacc[nt][3],
                             pah[kk][0], pah[kk][1], pah[kk][2], pah[kk][3],
                             bvh[nt][0], bvh[nt][1]);
                    MMA_BF16(oacc[nt][0], oacc[nt][1], oacc[nt][2], oacc[nt][3],
                             pal[kk][0], pal[kk][1], pal[kk][2], pal[kk][3],
                             bvh[nt][0], bvh[nt][1]);
                    MMA_BF16(oacc[nt][0], oacc[nt][1], oacc[nt][2], oacc[nt][3],
                             pah[kk][0], pah[kk][1], pah[kk][2], pah[kk][3],
                             bvl[nt][0], bvl[nt][1]);
                }
            }
        }
        __syncthreads();
    }

    l0 += __shfl_xor_sync(0xFFFFFFFF, l0, 1);
    l0 += __shfl_xor_sync(0xFFFFFFFF, l0, 2);
    l1 += __shfl_xor_sync(0xFFFFFFFF, l1, 1);
    l1 += __shfl_xor_sync(0xFFFFFFFF, l1, 2);
    const float inv0 = 1.0f / l0;
    const float inv1 = 1.0f / l1;

    // write a3 [hi|lo|hi] directly
    const size_t row0 = (size_t)(b * T_ + m0w + r0);
#pragma unroll
    for (int nt = 0; nt < 8; nt++) {
        const int col = h * 64 + nt * 8 + c0;
        float o0 = oacc[nt][0] * inv0, o1 = oacc[nt][1] * inv0;
        float o2 = oacc[nt][2] * inv1, o3 = oacc[nt][3] * inv1;
        uint32_t h0 = packbf(o0, o1), h1 = packbf(o2, o3);
        uint32_t lo0 = packbf(o0 - bflo(h0), o1 - bfhi(h0));
        uint32_t lo1 = packbf(o2 - bflo(h1), o3 - bfhi(h1));
        __nv_bfloat16* b0p = a3 + row0 * K3 + col;
        __nv_bfloat16* b1p = a3 + (row0 + 8) * K3 + col;
        *(uint32_t*)(b0p) = h0;  *(uint32_t*)(b0p + 1024) = lo0;  *(uint32_t*)(b0p + 2048) = h0;
        *(uint32_t*)(b1p) = h1;  *(uint32_t*)(b1p + 1024) = lo1;  *(uint32_t*)(b1p + 2048) = h1;
    }
}

// ---------------------------------------------------------------------------
// Inputs: 0 x, 1 mask, 2 Wq, 3 bq, 4 Wk, 5 Wv, 6 bv, 7 Wo, 8 bo
// ---------------------------------------------------------------------------
extern "C" void kernel_launch(void* const* d_in, const int* in_sizes, int n_in,
                              void* d_out, int out_size) {
    (void)in_sizes; (void)n_in; (void)out_size;
    const float* x  = (const float*)d_in[0];
    const float* Wq = (const float*)d_in[2];
    const float* bq = (const float*)d_in[3];
    const float* Wk = (const float*)d_in[4];
    const float* Wv = (const float*)d_in[5];
    const float* bv = (const float*)d_in[6];
    const float* Wo = (const float*)d_in[7];
    const float* bo = (const float*)d_in[8];
    float* out = (float*)d_out;

    int8_t *xi, *wi;
    __nv_bfloat16 *qh, *ql, *kh, *kl, *vh, *vl, *vth, *vtl, *a3, *wo3;
    cudaGetSymbolAddress((void**)&xi, g_xi);
    cudaGetSymbolAddress((void**)&wi, g_wi);
    cudaGetSymbolAddress((void**)&qh, g_qh);
    cudaGetSymbolAddress((void**)&ql, g_ql);
    cudaGetSymbolAddress((void**)&kh, g_kh);
    cudaGetSymbolAddress((void**)&kl, g_kl);
    cudaGetSymbolAddress((void**)&vh, g_vh);
    cudaGetSymbolAddress((void**)&vl, g_vl);
    cudaGetSymbolAddress((void**)&vth, g_vth);
    cudaGetSymbolAddress((void**)&vtl, g_vtl);
    cudaGetSymbolAddress((void**)&a3, g_a3);
    cudaGetSymbolAddress((void**)&wo3, g_wo3);

    cudaFuncSetAttribute(gemm_i8_qkv, cudaFuncAttributeMaxDynamicSharedMemorySize, SM_GI);
    cudaFuncSetAttribute(gemm_o, cudaFuncAttributeMaxDynamicSharedMemorySize, SM_GEMM);
    cudaFuncSetAttribute(attn_mma, cudaFuncAttributeMaxDynamicSharedMemorySize, AT_SMEM);

    const int nx4 = NELT / 4;
    const int nw4 = (D_ * D_) / 4;
    const int nw2 = (D_ * D_) / 2;
    quanti8<<<(nx4 + 255) / 256, 256>>>(x, xi, nx4, SX, 0);
    quanti8<<<(nw4 + 255) / 256, 256>>>(Wq, wi + (size_t)0 * D_ * K4I, nw4, SW, 1);
    quanti8<<<(nw4 + 255) / 256, 256>>>(Wk, wi + (size_t)1 * D_ * K4I, nw4, SW, 1);
    quanti8<<<(nw4 + 255) / 256, 256>>>(Wv, wi + (size_t)2 * D_ * K4I, nw4, SW, 1);
    split3w<<<(nw2 + 255) / 256, 256>>>(Wo, wo3, nw2);

    dim3 qkvgrid(3 * D_ / 128, M_ / 128);   // (24, 64)
    gemm_i8_qkv<<<qkvgrid, 128, SM_GI>>>(xi, wi, bq, bv, qh, ql, kh, kl, vh, vl);

    dim3 tgrid(T_ / 64, H_, B_);
    transp_v<<<tgrid, 128>>>(vh, vl, vth, vtl);

    dim3 agrid(T_ / 128, H_, B_);
    attn_mma<<<agrid, 256, AT_SMEM>>>(qh, ql, kh, kl, vth, vtl, a3);

    dim3 ogrid(D_ / 128, M_ / 128);         // (8, 64)
    gemm_o<<<ogrid, 128, SM_GEMM>>>(a3, wo3, bo, out);
}

// round 9
// speedup vs baseline: 2.6864x; 2.6864x over previous
#include <cuda_runtime.h>
#include <cuda_bf16.h>
#include <cuda_fp16.h>
#include <cstdint>

#define B_ 8
#define T_ 1024
#define D_ 1024
#define H_ 16
#define HD 64
#define M_ (B_ * T_)     // 8192
#define NELT (M_ * D_)   // 8388608
#define NIT16 (D_ / 64)  // 16 k-iters for fp16 GEMM (K=1024, BK=64)

// ---------------- scratch (static __device__; no cudaMalloc allowed) --------
__device__ __align__(256) __half g_x16[NELT];
__device__ __align__(256) __half g_w16[(size_t)3 * D_ * D_];   // [Wq;Wk;Wv] rows
__device__ __align__(256) __half g_wo16[(size_t)D_ * D_];
__device__ __align__(256) __half g_a16[NELT];

__device__ __align__(256) __nv_bfloat16 g_qh[NELT];
__device__ __align__(256) __nv_bfloat16 g_ql[NELT];
__device__ __align__(256) __nv_bfloat16 g_kh[NELT];
__device__ __align__(256) __nv_bfloat16 g_kl[NELT];
__device__ __align__(256) __nv_bfloat16 g_vh[NELT];
__device__ __align__(256) __nv_bfloat16 g_vl[NELT];
__device__ __align__(256) __nv_bfloat16 g_vth[NELT];
__device__ __align__(256) __nv_bfloat16 g_vtl[NELT];

// ---------------- helpers ---------------------------------------------------
__device__ __forceinline__ uint32_t smem_u32(const void* p) {
    uint32_t a;
    asm("{ .reg .u64 t; cvta.to.shared.u64 t, %1; cvt.u32.u64 %0, t; }" : "=r"(a) : "l"(p));
    return a;
}
__device__ __forceinline__ uint32_t swz(uint32_t off) { return off ^ ((off >> 3) & 0x70); }

#define CP_ASYNC16(dst, src) \
    asm volatile("cp.async.cg.shared.global [%0], [%1], 16;" :: "r"(dst), "l"(src))
#define CP_COMMIT()  asm volatile("cp.async.commit_group;" ::: "memory")
#define CP_WAIT1()   asm volatile("cp.async.wait_group 1;" ::: "memory")

#define LDSM_X4(r0, r1, r2, r3, addr) \
    asm volatile("ldmatrix.sync.aligned.m8n8.x4.shared.b16 {%0,%1,%2,%3}, [%4];" \
        : "=r"(r0), "=r"(r1), "=r"(r2), "=r"(r3) : "r"(addr))

#define MMA_BF16(c0, c1, c2, c3, a0, a1, a2, a3, b0, b1) \
    asm volatile("mma.sync.aligned.m16n8k16.row.col.f32.bf16.bf16.f32 " \
        "{%0,%1,%2,%3}, {%4,%5,%6,%7}, {%8,%9}, {%0,%1,%2,%3};" \
        : "+f"(c0), "+f"(c1), "+f"(c2), "+f"(c3) \
        : "r"(a0), "r"(a1), "r"(a2), "r"(a3), "r"(b0), "r"(b1))

#define MMA_F16(c0, c1, c2, c3, a0, a1, a2, a3, b0, b1) \
    asm volatile("mma.sync.aligned.m16n8k16.row.col.f32.f16.f16.f32 " \
        "{%0,%1,%2,%3}, {%4,%5,%6,%7}, {%8,%9}, {%0,%1,%2,%3};" \
        : "+f"(c0), "+f"(c1), "+f"(c2), "+f"(c3) \
        : "r"(a0), "r"(a1), "r"(a2), "r"(a3), "r"(b0), "r"(b1))

__device__ __forceinline__ uint32_t packbf(float lo, float hi) {
    uint32_t r;
    asm("cvt.rn.bf16x2.f32 %0, %1, %2;" : "=r"(r) : "f"(hi), "f"(lo));
    return r;
}
__device__ __forceinline__ float bflo(uint32_t u) { return __int_as_float(u << 16); }
__device__ __forceinline__ float bfhi(uint32_t u) { return __int_as_float(u & 0xFFFF0000u); }

__device__ __forceinline__ float fexp2(float y) {
    y = fmaxf(y, -126.0f);
    float t = y + 12582912.0f;
    int i = __float_as_int(t) - 0x4B400000;
    float f = y - (t - 12582912.0f);
    float p = 0.001333356f;
    p = fmaf(p, f, 0.009618129f);
    p = fmaf(p, f, 0.05550411f);
    p = fmaf(p, f, 0.2402265f);
    p = fmaf(p, f, 0.6931472f);
    p = fmaf(p, f, 1.0f);
    return p * __int_as_float((i + 127) << 23);
}

// ---------------- fp32 -> fp16 convert --------------------------------------
__global__ void cvt16(const float* __restrict__ s, __half* __restrict__ d, int n4) {
    int i = blockIdx.x * blockDim.x + threadIdx.x;
    if (i >= n4) return;
    float4 v = ((const float4*)s)[i];
    __half2 h0 = __floats2half2_rn(v.x, v.y);
    __half2 h1 = __floats2half2_rn(v.z, v.w);
    ((__half2*)d)[2 * i + 0] = h0;
    ((__half2*)d)[2 * i + 1] = h1;
}

// ---------------- fp16 HMMA GEMM (K=1024) ------------------------------------
// 128 threads, 4 warps 64x64, CTA 128x128, 3-stage cp.async, 2 CTA/SM.
// MODE 0: fused QKV (N=3072) -> bf16 hi/lo per region + bias
// MODE 1: O-projection -> float C + bias
#define STAGE_B 32768
#define SM_GEMM (3 * STAGE_B)

template <int MODE>
__global__ __launch_bounds__(128, 2)
void gemm16(const __half* __restrict__ A2, const __half* __restrict__ B2,
            const float* __restrict__ bq, const float* __restrict__ bvv,
            const float* __restrict__ bo,
            __nv_bfloat16* __restrict__ qh, __nv_bfloat16* __restrict__ ql,
            __nv_bfloat16* __restrict__ kh, __nv_bfloat16* __restrict__ kl,
            __nv_bfloat16* __restrict__ vh, __nv_bfloat16* __restrict__ vl,
            float* __restrict__ C) {
    extern __shared__ char smem[];
    const uint32_t sbase = smem_u32(smem);
    const int tid = threadIdx.x;
    const int wid = tid >> 5;
    const int lane = tid & 31;
    const int m0 = blockIdx.y * 128;
    const int n0 = blockIdx.x * 128;

    const int r_ld = tid >> 3;
    const int c_ld = tid & 7;

    const __half* Abase = A2 + (size_t)(m0 + r_ld * 8) * D_ + c_ld * 8;
    const __half* Bbase = B2 + (size_t)(n0 + r_ld * 8) * D_ + c_ld * 8;

    float acc[4][8][4];
#pragma unroll
    for (int i = 0; i < 4; i++)
#pragma unroll
        for (int j = 0; j < 8; j++)
#pragma unroll
            for (int t = 0; t < 4; t++) acc[i][j][t] = 0.0f;

    auto load_stage = [&](int stage, int kt) {
        const uint32_t sA = sbase + stage * STAGE_B;
        const uint32_t sB = sA + 16384;
        const size_t koff = (size_t)kt * 64;
#pragma unroll
        for (int j = 0; j < 8; j++) {
            const int r = r_ld * 8 + j;
            CP_ASYNC16(sA + swz((uint32_t)(r * 128 + c_ld * 16)),
                       Abase + (size_t)j * D_ + koff);
        }
#pragma unroll
        for (int j = 0; j < 8; j++) {
            const int r = r_ld * 8 + j;
            CP_ASYNC16(sB + swz((uint32_t)(r * 128 + c_ld * 16)),
                       Bbase + (size_t)j * D_ + koff);
        }
    };

    load_stage(0, 0); CP_COMMIT();
    load_stage(1, 1); CP_COMMIT();

    const int wm = (wid & 1) * 64;
    const int wn = (wid >> 1) * 64;
    const int lrow = lane & 15;
    const int lkhalf = ((lane >> 4) & 1) * 16;

    for (int kt = 0; kt < NIT16; kt++) {
        CP_WAIT1();
        __syncthreads();
        if (kt + 2 < NIT16) load_stage((kt + 2) % 3, kt + 2);
        CP_COMMIT();

        const uint32_t sA = sbase + (kt % 3) * STAGE_B;
        const uint32_t sB = sA + 16384;

#pragma unroll
        for (int k16 = 0; k16 < 4; k16++) {
            const uint32_t kb = k16 * 32 + lkhalf;
            uint32_t a[4][4], b[8][2];
#pragma unroll
            for (int mt = 0; mt < 4; mt++) {
                const uint32_t ad = sA + swz((uint32_t)((wm + mt * 16 + lrow) * 128) + kb);
                LDSM_X4(a[mt][0], a[mt][1], a[mt][2], a[mt][3], ad);
            }
#pragma unroll
            for (int np = 0; np < 4; np++) {
                const uint32_t bd = sB + swz((uint32_t)((wn + np * 16 + lrow) * 128) + kb);
                LDSM_X4(b[2 * np][0], b[2 * np + 1][0], b[2 * np][1], b[2 * np + 1][1], bd);
            }
#pragma unroll
            for (int mt = 0; mt < 4; mt++)
#pragma unroll
                for (int nt = 0; nt < 8; nt++)
                    MMA_F16(acc[mt][nt][0], acc[mt][nt][1], acc[mt][nt][2], acc[mt][nt][3],
                            a[mt][0], a[mt][1], a[mt][2], a[mt][3],
                            b[nt][0], b[nt][1]);
        }
    }

    // ---- epilogue ----
    const int em = m0 + wm + (lane >> 2);
    const int region = n0 >> 10;
    const int nbase = (MODE == 0 ? (n0 & 1023) : n0) + wn + (lane & 3) * 2;

    const float* bias = (MODE == 1) ? bo : (region == 0 ? bq : (region == 2 ? bvv : nullptr));
    __nv_bfloat16* Dhi = nullptr;
    __nv_bfloat16* Dlo = nullptr;
    if (MODE == 0) {
        if (region == 0) { Dhi = qh; Dlo = ql; }
        else if (region == 1) { Dhi = kh; Dlo = kl; }
        else { Dhi = vh; Dlo = vl; }
    }

#pragma unroll
    for (int mt = 0; mt < 4; mt++) {
#pragma unroll
        for (int nt = 0; nt < 8; nt++) {
            const int n = nbase + nt * 8;
            float2 bb = make_float2(0.f, 0.f);
            if (bias) bb = *(const float2*)(bias + n);
            float v0 = acc[mt][nt][0] + bb.x, v1 = acc[mt][nt][1] + bb.y;
            float v2 = acc[mt][nt][2] + bb.x, v3 = acc[mt][nt][3] + bb.y;
            const size_t r0 = (size_t)(em + mt * 16) * D_ + n;
            const size_t r1 = (size_t)(em + mt * 16 + 8) * D_ + n;
            if (MODE == 0) {
                uint32_t h0 = packbf(v0, v1), h1 = packbf(v2, v3);
                *(uint32_t*)(Dhi + r0) = h0;
                *(uint32_t*)(Dhi + r1) = h1;
                *(uint32_t*)(Dlo + r0) = packbf(v0 - bflo(h0), v1 - bfhi(h0));
                *(uint32_t*)(Dlo + r1) = packbf(v2 - bflo(h1), v3 - bfhi(h1));
            } else {
                *(float2*)(C + r0) = make_float2(v0, v1);
                *(float2*)(C + r1) = make_float2(v2, v3);
            }
        }
    }
}

// ---------------- V transpose ------------------------------------------------
__global__ __launch_bounds__(128, 4)
void transp_v(const __nv_bfloat16* __restrict__ vh, const __nv_bfloat16* __restrict__ vl,
              __nv_bfloat16* __restrict__ vth, __nv_bfloat16* __restrict__ vtl) {
    __shared__ __nv_bfloat16 s[64][72];
    const int tid = threadIdx.x;
    const int tt = blockIdx.x, h = blockIdx.y, b = blockIdx.z;
    const __nv_bfloat16* src[2] = {vh, vl};
    __nv_bfloat16* dst[2] = {vth, vtl};
#pragma unroll
    for (int m = 0; m < 2; m++) {
        __syncthreads();
#pragma unroll
        for (int it = 0; it < 4; it++) {
            const int idx = it * 128 + tid;
            const int r = idx >> 3, c8 = idx & 7;
            *(uint4*)&s[r][c8 * 8] =
                *(const uint4*)(src[m] + (size_t)(b * T_ + tt * 64 + r) * D_ + h * 64 + c8 * 8);
        }
        __syncthreads();
#pragma unroll
        for (int it = 0; it < 4; it++) {
            const int idx = it * 128 + tid;
            const int d = idx >> 3, t8 = idx & 7;
            __nv_bfloat16 tmp[8];
#pragma unroll
            for (int j = 0; j < 8; j++) tmp[j] = s[t8 * 8 + j][d];
            *(uint4*)(dst[m] + (size_t)((b * H_ + h) * 64 + d) * T_ + tt * 64 + t8 * 8) =
                *(uint4*)tmp;
        }
    }
}

// ---------------- tensor-core causal flash attention (bf16x3 interior) -------
// epilogue writes fp16 a16 [M,1024] directly for the fp16 O-GEMM.
#define AT_SQ    32768
#define AT_STAGE 32768
#define AT_SMEM  (AT_SQ + 3 * AT_STAGE)

__global__ __launch_bounds__(256, 1)
void attn_mma(const __nv_bfloat16* __restrict__ qh_, const __nv_bfloat16* __restrict__ ql_,
              const __nv_bfloat16* __restrict__ kh_, const __nv_bfloat16* __restrict__ kl_,
              const __nv_bfloat16* __restrict__ vth_, const __nv_bfloat16* __restrict__ vtl_,
              __half* __restrict__ a16) {
    extern __shared__ char smem[];
    const uint32_t sbase = smem_u32(smem);
    const int tid = threadIdx.x;
    const int wid = tid >> 5;
    const int lane = tid & 31;
    const int iq = blockIdx.x;
    const int h  = blockIdx.y;
    const int b  = blockIdx.z;
    const int nblocks = 2 * iq + 2;

    {
        const __nv_bfloat16* qs[2] = {qh_, ql_};
#pragma unroll
        for (int m = 0; m < 2; m++)
#pragma unroll
            for (int it = 0; it < 4; it++) {
                const int idx = it * 256 + tid;
                const int r = idx >> 3, c = idx & 7;
                CP_ASYNC16(sbase + m * 16384 + swz((uint32_t)(r * 128 + c * 16)),
                           qs[m] + (size_t)(b * T_ + iq * 128 + r) * D_ + h * 64 + c * 8);
            }
    }
    auto pf_kv = [&](int jb) {
        const uint32_t s0 = sbase + AT_SQ + (jb % 3) * AT_STAGE;
        const __nv_bfloat16* ks[2] = {kh_, kl_};
        const __nv_bfloat16* vs[2] = {vth_, vtl_};
#pragma unroll
        for (int m = 0; m < 2; m++)
#pragma unroll
            for (int it = 0; it < 2; it++) {
                const int idx = it * 256 + tid;
                const int r = idx >> 3, c = idx & 7;
                CP_ASYNC16(s0 + m * 8192 + swz((uint32_t)(r * 128 + c * 16)),
                           ks[m] + (size_t)(b * T_ + jb * 64 + r) * D_ + h * 64 + c * 8);
            }
#pragma unroll
        for (int m = 0; m < 2; m++)
#pragma unroll
            for (int it = 0; it < 2; it++) {
                const int idx = it * 256 + tid;
                const int r = idx >> 3, c = idx & 7;
                CP_ASYNC16(s0 + 16384 + m * 8192 + swz((uint32_t)(r * 128 + c * 16)),
                           vs[m] + (size_t)((b * H_ + h) * 64 + r) * T_ + jb * 64 + c * 8);
            }
    };

    pf_kv(0); CP_COMMIT();
    if (nblocks > 1) pf_kv(1);
    CP_COMMIT();

    float oacc[8][4];
#pragma unroll
    for (int i = 0; i < 8; i++)
#pragma unroll
        for (int j = 0; j < 4; j++) oacc[i][j] = 0.0f;
    float l0 = 0.0f, l1 = 0.0f;

    const int m0w = iq * 128 + wid * 16;
    const int r0 = lane >> 2;
    const int c0 = (lane & 3) * 2;
    const int lrow = lane & 15;
    const int lkh = ((lane >> 4) & 1) * 16;

    for (int jb = 0; jb < nblocks; jb++) {
        CP_WAIT1();
        __syncthreads();
        if (jb + 2 < nblocks) pf_kv(jb + 2);
        CP_COMMIT();

        const uint32_t sK = sbase + AT_SQ + (jb % 3) * AT_STAGE;
        const uint32_t sV = sK + 16384;

        if (jb * 64 <= m0w + 15) {
            float sfr[8][4];
#pragma unroll
            for (int i = 0; i < 8; i++)
#pragma unroll
                for (int j = 0; j < 4; j++) sfr[i][j] = 0.0f;

#pragma unroll
            for (int k16 = 0; k16 < 4; k16++) {
                const uint32_t kb = k16 * 32 + lkh;
                uint32_t ah[4], al[4], bh[8][2], bl[8][2];
                LDSM_X4(ah[0], ah[1], ah[2], ah[3],
                        sbase + swz((uint32_t)((wid * 16 + lrow) * 128) + kb));
                LDSM_X4(al[0], al[1], al[2], al[3],
                        sbase + 16384 + swz((uint32_t)((wid * 16 + lrow) * 128) + kb));
#pragma unroll
                for (int np = 0; np < 4; np++) {
                    const uint32_t off = swz((uint32_t)((np * 16 + lrow) * 128) + kb);
                    LDSM_X4(bh[2 * np][0], bh[2 * np + 1][0], bh[2 * np][1], bh[2 * np + 1][1],
                            sK + off);
                    LDSM_X4(bl[2 * np][0], bl[2 * np + 1][0], bl[2 * np][1], bl[2 * np + 1][1],
                            sK + 8192 + off);
                }
#pragma unroll
                for (int nt = 0; nt < 8; nt++) {
                    MMA_BF16(sfr[nt][0], sfr[nt][1], sfr[nt][2], sfr[nt][3],
                             ah[0], ah[1], ah[2], ah[3], bh[nt][0], bh[nt][1]);
                    MMA_BF16(sfr[nt][0], sfr[nt][1], sfr[nt][2], sfr[nt][3],
                             al[0], al[1], al[2], al[3], bh[nt][0], bh[nt][1]);
                    MMA_BF16(sfr[nt][0], sfr[nt][1], sfr[nt][2], sfr[nt][3],
                             ah[0], ah[1], ah[2], ah[3], bl[nt][0], bl[nt][1]);
                }
            }

            const bool needmask = (jb * 64 + 63 > m0w);
#pragma unroll
            for (int nt = 0; nt < 8; nt++) {
#pragma unroll
                for (int e = 0; e < 4; e++) {
                    const int col_g = jb * 64 + nt * 8 + c0 + (e & 1);
                    const int row_g = m0w + r0 + ((e >> 1) << 3);
                    float p = fexp2(sfr[nt][e] * 0.1803368801f);
                    if (needmask && col_g > row_g) p = 0.0f;
                    sfr[nt][e] = p;
                    if (e < 2) l0 += p; else l1 += p;
                }
            }

            uint32_t pah[4][4], pal[4][4];
#pragma unroll
            for (int kk = 0; kk < 4; kk++) {
                const float* t0 = sfr[2 * kk];
                const float* t1 = sfr[2 * kk + 1];
                pah[kk][0] = packbf(t0[0], t0[1]);
                pah[kk][1] = packbf(t0[2], t0[3]);
                pah[kk][2] = packbf(t1[0], t1[1]);
                pah[kk][3] = packbf(t1[2], t1[3]);
                pal[kk][0] = packbf(t0[0] - bflo(pah[kk][0]), t0[1] - bfhi(pah[kk][0]));
                pal[kk][1] = packbf(t0[2] - bflo(pah[kk][1]), t0[3] - bfhi(pah[kk][1]));
                pal[kk][2] = packbf(t1[0] - bflo(pah[kk][2]), t1[1] - bfhi(pah[kk][2]));
                pal[kk][3] = packbf(t1[2] - bflo(pah[kk][3]), t1[3] - bfhi(pah[kk][3]));
            }

#pragma unroll
            for (int kk = 0; kk < 4; kk++) {
                const uint32_t kb = kk * 32 + lkh;
                uint32_t bvh[8][2], bvl[8][2];
#pragma unroll
                for (int np = 0; np < 4; np++) {
                    const uint32_t off = swz((uint32_t)((np * 16 + lrow) * 128) + kb);
                    LDSM_X4(bvh[2 * np][0], bvh[2 * np + 1][0], bvh[2 * np][1], bvh[2 * np + 1][1],
                            sV + off);
                    LDSM_X4(bvl[2 * np][0], bvl[2 * np + 1][0], bvl[2 * np][1], bvl[2 * np + 1][1],
                            sV + 8192 + off);
                }
#pragma unroll
                for (int nt = 0; nt < 8; nt++) {
                    MMA_BF16(oacc[nt][0], oacc[nt][1], oacc[nt][2], oacc[nt][3],
                             pah[kk][0], pah[kk][1], pah[kk][2], pah[kk][3],
                             bvh[nt][0], bvh[nt][1]);
                    MMA_BF16(oacc[nt][0], oacc[nt][1], oacc[nt][2], oacc[nt][3],
                             pal[kk][0], pal[kk][1], pal[kk][2], pal[kk][3],
                             bvh[nt][0], bvh[nt][1]);
                    MMA_BF16(oacc[nt][0], oacc[nt][1], oacc[nt][2], oacc[nt][3],
                             pah[kk][0], pah[kk][1], pah[kk][2], pah[kk][3],
                             bvl[nt][0], bvl[nt][1]);
                }
            }
        }
        __syncthreads();
    }

    l0 += __shfl_xor_sync(0xFFFFFFFF, l0, 1);
    l0 += __shfl_xor_sync(0xFFFFFFFF, l0, 2);
    l1 += __shfl_xor_sync(0xFFFFFFFF, l1, 1);
    l1 += __shfl_xor_sync(0xFFFFFFFF, l1, 2);
    const float inv0 = 1.0f / l0;
    const float inv1 = 1.0f / l1;

    // write fp16 attention output directly
    const size_t row0 = (size_t)(b * T_ + m0w + r0);
#pragma unroll
    for (int nt = 0; nt < 8; nt++) {
        const int col = h * 64 + nt * 8 + c0;
        *(__half2*)(a16 + row0 * D_ + col) =
            __floats2half2_rn(oacc[nt][0] * inv0, oacc[nt][1] * inv0);
        *(__half2*)(a16 + (row0 + 8) * D_ + col) =
            __floats2half2_rn(oacc[nt][2] * inv1, oacc[nt][3] * inv1);
    }
}

// ---------------------------------------------------------------------------
// Inputs: 0 x, 1 mask, 2 Wq, 3 bq, 4 Wk, 5 Wv, 6 bv, 7 Wo, 8 bo
// ---------------------------------------------------------------------------
extern "C" void kernel_launch(void* const* d_in, const int* in_sizes, int n_in,
                              void* d_out, int out_size) {
    (void)in_sizes; (void)n_in; (void)out_size;
    const float* x  = (const float*)d_in[0];
    const float* Wq = (const float*)d_in[2];
    const float* bq = (const float*)d_in[3];
    const float* Wk = (const float*)d_in[4];
    const float* Wv = (const float*)d_in[5];
    const float* bv = (const float*)d_in[6];
    const float* Wo = (const float*)d_in[7];
    const float* bo = (const float*)d_in[8];
    float* out = (float*)d_out;

    __half *x16, *w16, *wo16, *a16;
    __nv_bfloat16 *qh, *ql, *kh, *kl, *vh, *vl, *vth, *vtl;
    cudaGetSymbolAddress((void**)&x16, g_x16);
    cudaGetSymbolAddress((void**)&w16, g_w16);
    cudaGetSymbolAddress((void**)&wo16, g_wo16);
    cudaGetSymbolAddress((void**)&a16, g_a16);
    cudaGetSymbolAddress((void**)&qh, g_qh);
    cudaGetSymbolAddress((void**)&ql, g_ql);
    cudaGetSymbolAddress((void**)&kh, g_kh);
    cudaGetSymbolAddress((void**)&kl, g_kl);
    cudaGetSymbolAddress((void**)&vh, g_vh);
    cudaGetSymbolAddress((void**)&vl, g_vl);
    cudaGetSymbolAddress((void**)&vth, g_vth);
    cudaGetSymbolAddress((void**)&vtl, g_vtl);

    cudaFuncSetAttribute(gemm16<0>, cudaFuncAttributeMaxDynamicSharedMemorySize, SM_GEMM);
    cudaFuncSetAttribute(gemm16<1>, cudaFuncAttributeMaxDynamicSharedMemorySize, SM_GEMM);
    cudaFuncSetAttribute(attn_mma, cudaFuncAttributeMaxDynamicSharedMemorySize, AT_SMEM);

    const int nx4 = NELT / 4;
    const int nw4 = (D_ * D_) / 4;
    cvt16<<<(nx4 + 255) / 256, 256>>>(x, x16, nx4);
    cvt16<<<(nw4 + 255) / 256, 256>>>(Wq, w16 + (size_t)0 * D_ * D_, nw4);
    cvt16<<<(nw4 + 255) / 256, 256>>>(Wk, w16 + (size_t)1 * D_ * D_, nw4);
    cvt16<<<(nw4 + 255) / 256, 256>>>(Wv, w16 + (size_t)2 * D_ * D_, nw4);
    cvt16<<<(nw4 + 255) / 256, 256>>>(Wo, wo16, nw4);

    // fused QKV: N = 3072, K = 1024
    dim3 qkvgrid(3 * D_ / 128, M_ / 128);   // (24, 64)
    gemm16<0><<<qkvgrid, 128, SM_GEMM>>>(x16, w16, bq, bv, nullptr,
                                         qh, ql, kh, kl, vh, vl, nullptr);

    dim3 tgrid(T_ / 64, H_, B_);
    transp_v<<<tgrid, 128>>>(vh, vl, vth, vtl);

    dim3 agrid(T_ / 128, H_, B_);
    attn_mma<<<agrid, 256, AT_SMEM>>>(qh, ql, kh, kl, vth, vtl, a16);

    dim3 ogrid(D_ / 128, M_ / 128);         // (8, 64)
    gemm16<1><<<ogrid, 128, SM_GEMM>>>(a16, wo16, nullptr, nullptr, bo,
                                       nullptr, nullptr, nullptr, nullptr, nullptr, nullptr, out);
}

// round 11
// speedup vs baseline: 5.3347x; 1.9858x over previous
#include <cuda_runtime.h>
#include <cuda_fp16.h>
#include <cstdint>

#define B_ 8
#define T_ 1024
#define D_ 1024
#define H_ 16
#define HD 64
#define M_ (B_ * T_)     // 8192
#define NELT (M_ * D_)   // 8388608
#define NIT16 (D_ / 64)  // 16 k-iters (K=1024, BK=64)

// ---------------- scratch (static __device__; no cudaMalloc allowed) --------
__device__ __align__(256) __half g_x16[NELT];
__device__ __align__(256) __half g_w16[(size_t)3 * D_ * D_];   // [Wq;Wk;Wv]
__device__ __align__(256) __half g_wo16[(size_t)D_ * D_];
__device__ __align__(256) __half g_a16[NELT];

__device__ __align__(256) __half g_q16[NELT];
__device__ __align__(256) __half g_k16[NELT];
__device__ __align__(256) __half g_v16[NELT];
__device__ __align__(256) __half g_vt16[NELT];

// ---------------- helpers ---------------------------------------------------
__device__ __forceinline__ uint32_t smem_u32(const void* p) {
    uint32_t a;
    asm("{ .reg .u64 t; cvta.to.shared.u64 t, %1; cvt.u32.u64 %0, t; }" : "=r"(a) : "l"(p));
    return a;
}
__device__ __forceinline__ uint32_t swz(uint32_t off) { return off ^ ((off >> 3) & 0x70); }

#define CP_ASYNC16(dst, src) \
    asm volatile("cp.async.cg.shared.global [%0], [%1], 16;" :: "r"(dst), "l"(src))
#define CP_COMMIT()  asm volatile("cp.async.commit_group;" ::: "memory")
#define CP_WAIT1()   asm volatile("cp.async.wait_group 1;" ::: "memory")

#define LDSM_X4(r0, r1, r2, r3, addr) \
    asm volatile("ldmatrix.sync.aligned.m8n8.x4.shared.b16 {%0,%1,%2,%3}, [%4];" \
        : "=r"(r0), "=r"(r1), "=r"(r2), "=r"(r3) : "r"(addr))

#define MMA_F16(c0, c1, c2, c3, a0, a1, a2, a3, b0, b1) \
    asm volatile("mma.sync.aligned.m16n8k16.row.col.f32.f16.f16.f32 " \
        "{%0,%1,%2,%3}, {%4,%5,%6,%7}, {%8,%9}, {%0,%1,%2,%3};" \
        : "+f"(c0), "+f"(c1), "+f"(c2), "+f"(c3) \
        : "r"(a0), "r"(a1), "r"(a2), "r"(a3), "r"(b0), "r"(b1))

__device__ __forceinline__ uint32_t packh(float lo, float hi) {
    __half2 h = __floats2half2_rn(lo, hi);
    return *(uint32_t*)&h;
}

__device__ __forceinline__ float fexp2(float y) {
    y = fmaxf(y, -126.0f);
    float t = y + 12582912.0f;
    int i = __float_as_int(t) - 0x4B400000;
    float f = y - (t - 12582912.0f);
    float p = 0.001333356f;
    p = fmaf(p, f, 0.009618129f);
    p = fmaf(p, f, 0.05550411f);
    p = fmaf(p, f, 0.2402265f);
    p = fmaf(p, f, 0.6931472f);
    p = fmaf(p, f, 1.0f);
    return p * __int_as_float((i + 127) << 23);
}

// ---------------- fp32 -> fp16 convert --------------------------------------
__global__ void cvt16(const float* __restrict__ s, __half* __restrict__ d, int n4) {
    int i = blockIdx.x * blockDim.x + threadIdx.x;
    if (i >= n4) return;
    float4 v = ((const float4*)s)[i];
    ((__half2*)d)[2 * i + 0] = __floats2half2_rn(v.x, v.y);
    ((__half2*)d)[2 * i + 1] = __floats2half2_rn(v.z, v.w);
}

// ---------------- fp16 HMMA GEMM (K=1024) ------------------------------------
// 128 threads, 4 warps 64x64, CTA 128x128, 3-stage cp.async, 2 CTA/SM.
// MODE 0: fused QKV (N=3072) -> fp16 q/k/v + bias   MODE 1: O-proj -> fp32 + bias
#define STAGE_B 32768
#define SM_GEMM (3 * STAGE_B)

template <int MODE>
__global__ __launch_bounds__(128, 2)
void gemm16(const __half* __restrict__ A2, const __half* __restrict__ B2,
            const float* __restrict__ bq, const float* __restrict__ bvv,
            const float* __restrict__ bo,
            __half* __restrict__ q16, __half* __restrict__ k16,
            __half* __restrict__ v16, float* __restrict__ C) {
    extern __shared__ char smem[];
    const uint32_t sbase = smem_u32(smem);
    const int tid = threadIdx.x;
    const int wid = tid >> 5;
    const int lane = tid & 31;
    const int m0 = blockIdx.y * 128;
    const int n0 = blockIdx.x * 128;

    const int r_ld = tid >> 3;
    const int c_ld = tid & 7;

    const __half* Abase = A2 + (size_t)(m0 + r_ld * 8) * D_ + c_ld * 8;
    const __half* Bbase = B2 + (size_t)(n0 + r_ld * 8) * D_ + c_ld * 8;

    float acc[4][8][4];
#pragma unroll
    for (int i = 0; i < 4; i++)
#pragma unroll
        for (int j = 0; j < 8; j++)
#pragma unroll
            for (int t = 0; t < 4; t++) acc[i][j][t] = 0.0f;

    auto load_stage = [&](int stage, int kt) {
        const uint32_t sA = sbase + stage * STAGE_B;
        const uint32_t sB = sA + 16384;
        const size_t koff = (size_t)kt * 64;
#pragma unroll
        for (int j = 0; j < 8; j++) {
            const int r = r_ld * 8 + j;
            CP_ASYNC16(sA + swz((uint32_t)(r * 128 + c_ld * 16)),
                       Abase + (size_t)j * D_ + koff);
        }
#pragma unroll
        for (int j = 0; j < 8; j++) {
            const int r = r_ld * 8 + j;
            CP_ASYNC16(sB + swz((uint32_t)(r * 128 + c_ld * 16)),
                       Bbase + (size_t)j * D_ + koff);
        }
    };

    load_stage(0, 0); CP_COMMIT();
    load_stage(1, 1); CP_COMMIT();

    const int wm = (wid & 1) * 64;
    const int wn = (wid >> 1) * 64;
    const int lrow = lane & 15;
    const int lkhalf = ((lane >> 4) & 1) * 16;

    for (int kt = 0; kt < NIT16; kt++) {
        CP_WAIT1();
        __syncthreads();
        if (kt + 2 < NIT16) load_stage((kt + 2) % 3, kt + 2);
        CP_COMMIT();

        const uint32_t sA = sbase + (kt % 3) * STAGE_B;
        const uint32_t sB = sA + 16384;

#pragma unroll
        for (int k16 = 0; k16 < 4; k16++) {
            const uint32_t kb = k16 * 32 + lkhalf;
            uint32_t a[4][4], b[8][2];
#pragma unroll
            for (int mt = 0; mt < 4; mt++) {
                const uint32_t ad = sA + swz((uint32_t)((wm + mt * 16 + lrow) * 128) + kb);
                LDSM_X4(a[mt][0], a[mt][1], a[mt][2], a[mt][3], ad);
            }
#pragma unroll
            for (int np = 0; np < 4; np++) {
                const uint32_t bd = sB + swz((uint32_t)((wn + np * 16 + lrow) * 128) + kb);
                LDSM_X4(b[2 * np][0], b[2 * np + 1][0], b[2 * np][1], b[2 * np + 1][1], bd);
            }
#pragma unroll
            for (int mt = 0; mt < 4; mt++)
#pragma unroll
                for (int nt = 0; nt < 8; nt++)
                    MMA_F16(acc[mt][nt][0], acc[mt][nt][1], acc[mt][nt][2], acc[mt][nt][3],
                            a[mt][0], a[mt][1], a[mt][2], a[mt][3],
                            b[nt][0], b[nt][1]);
        }
    }

    // ---- epilogue ----
    const int em = m0 + wm + (lane >> 2);
    const int region = n0 >> 10;
    const int nbase = (MODE == 0 ? (n0 & 1023) : n0) + wn + (lane & 3) * 2;

    const float* bias = (MODE == 1) ? bo : (region == 0 ? bq : (region == 2 ? bvv : nullptr));
    __half* Dst = nullptr;
    if (MODE == 0) Dst = (region == 0 ? q16 : (region == 1 ? k16 : v16));

#pragma unroll
    for (int mt = 0; mt < 4; mt++) {
#pragma unroll
        for (int nt = 0; nt < 8; nt++) {
            const int n = nbase + nt * 8;
            float2 bb = make_float2(0.f, 0.f);
            if (bias) bb = *(const float2*)(bias + n);
            float v0 = acc[mt][nt][0] + bb.x, v1 = acc[mt][nt][1] + bb.y;
            float v2 = acc[mt][nt][2] + bb.x, v3 = acc[mt][nt][3] + bb.y;
            const size_t r0 = (size_t)(em + mt * 16) * D_ + n;
            const size_t r1 = (size_t)(em + mt * 16 + 8) * D_ + n;
            if (MODE == 0) {
                *(uint32_t*)(Dst + r0) = packh(v0, v1);
                *(uint32_t*)(Dst + r1) = packh(v2, v3);
            } else {
                *(float2*)(C + r0) = make_float2(v0, v1);
                *(float2*)(C + r1) = make_float2(v2, v3);
            }
        }
    }
}

// ---------------- V transpose: [b*T+t][h*64+d] -> [(b*H+h)*64+d][t] ----------
__global__ __launch_bounds__(128, 4)
void transp_v(const __half* __restrict__ v16, __half* __restrict__ vt16) {
    __shared__ __half s[64][72];
    const int tid = threadIdx.x;
    const int tt = blockIdx.x, h = blockIdx.y, b = blockIdx.z;
#pragma unroll
    for (int it = 0; it < 4; it++) {
        const int idx = it * 128 + tid;
        const int r = idx >> 3, c8 = idx & 7;
        *(uint4*)&s[r][c8 * 8] =
            *(const uint4*)(v16 + (size_t)(b * T_ + tt * 64 + r) * D_ + h * 64 + c8 * 8);
    }
    __syncthreads();
#pragma unroll
    for (int it = 0; it < 4; it++) {
        const int idx = it * 128 + tid;
        const int d = idx >> 3, t8 = idx & 7;
        __half tmp[8];
#pragma unroll
        for (int j = 0; j < 8; j++) tmp[j] = s[t8 * 8 + j][d];
        *(uint4*)(vt16 + (size_t)((b * H_ + h) * 64 + d) * T_ + tt * 64 + t8 * 8) =
            *(uint4*)tmp;
    }
}

// ---------------- single-term fp16 causal flash attention --------------------
// CTA: 128 q-rows x (b,h). 8 warps x 16 rows. Q 16KB + 3 stages x {K 8KB, V 8KB}.
#define AT_SQ    16384
#define AT_STAGE 16384
#define AT_SMEM  (AT_SQ + 3 * AT_STAGE)    // 65536

__global__ __launch_bounds__(256, 1)
void attn_mma(const __half* __restrict__ q16, const __half* __restrict__ k16,
              const __half* __restrict__ vt16, __half* __restrict__ a16) {
    extern __shared__ char smem[];
    const uint32_t sbase = smem_u32(smem);
    const int tid = threadIdx.x;
    const int wid = tid >> 5;
    const int lane = tid & 31;
    const int iq = blockIdx.x;
    const int h  = blockIdx.y;
    const int b  = blockIdx.z;
    const int nblocks = 2 * iq + 2;

    // stage Q
#pragma unroll
    for (int it = 0; it < 4; it++) {
        const int idx = it * 256 + tid;
        const int r = idx >> 3, c = idx & 7;
        CP_ASYNC16(sbase + swz((uint32_t)(r * 128 + c * 16)),
                   q16 + (size_t)(b * T_ + iq * 128 + r) * D_ + h * 64 + c * 8);
    }
    auto pf_kv = [&](int jb) {
        const uint32_t s0 = sbase + AT_SQ + (jb % 3) * AT_STAGE;
#pragma unroll
        for (int it = 0; it < 2; it++) {
            const int idx = it * 256 + tid;
            const int r = idx >> 3, c = idx & 7;
            CP_ASYNC16(s0 + swz((uint32_t)(r * 128 + c * 16)),
                       k16 + (size_t)(b * T_ + jb * 64 + r) * D_ + h * 64 + c * 8);
        }
#pragma unroll
        for (int it = 0; it < 2; it++) {
            const int idx = it * 256 + tid;
            const int r = idx >> 3, c = idx & 7;
            CP_ASYNC16(s0 + 8192 + swz((uint32_t)(r * 128 + c * 16)),
                       vt16 + (size_t)((b * H_ + h) * 64 + r) * T_ + jb * 64 + c * 8);
        }
    };

    pf_kv(0); CP_COMMIT();
    if (nblocks > 1) pf_kv(1);
    CP_COMMIT();

    float oacc[8][4];
#pragma unroll
    for (int i = 0; i < 8; i++)
#pragma unroll
        for (int j = 0; j < 4; j++) oacc[i][j] = 0.0f;
    float l0 = 0.0f, l1 = 0.0f;

    const int m0w = iq * 128 + wid * 16;
    const int r0 = lane >> 2;
    const int c0 = (lane & 3) * 2;
    const int lrow = lane & 15;
    const int lkh = ((lane >> 4) & 1) * 16;

    for (int jb = 0; jb < nblocks; jb++) {
        CP_WAIT1();
        __syncthreads();
        if (jb + 2 < nblocks) pf_kv(jb + 2);
        CP_COMMIT();

        const uint32_t sK = sbase + AT_SQ + (jb % 3) * AT_STAGE;
        const uint32_t sV = sK + 8192;

        if (jb * 64 <= m0w + 15) {
            float sfr[8][4];
#pragma unroll
            for (int i = 0; i < 8; i++)
#pragma unroll
                for (int j = 0; j < 4; j++) sfr[i][j] = 0.0f;

            // ---- S = Q K^T (single fp16 term) ----
#pragma unroll
            for (int k16i = 0; k16i < 4; k16i++) {
                const uint32_t kb = k16i * 32 + lkh;
                uint32_t a[4], bk[8][2];
                LDSM_X4(a[0], a[1], a[2], a[3],
                        sbase + swz((uint32_t)((wid * 16 + lrow) * 128) + kb));
#pragma unroll
                for (int np = 0; np < 4; np++) {
                    const uint32_t off = swz((uint32_t)((np * 16 + lrow) * 128) + kb);
                    LDSM_X4(bk[2 * np][0], bk[2 * np + 1][0], bk[2 * np][1], bk[2 * np + 1][1],
                            sK + off);
                }
#pragma unroll
                for (int nt = 0; nt < 8; nt++)
                    MMA_F16(sfr[nt][0], sfr[nt][1], sfr[nt][2], sfr[nt][3],
                            a[0], a[1], a[2], a[3], bk[nt][0], bk[nt][1]);
            }

            // ---- p = exp(s/8), causal mask, row sums ----
            const bool needmask = (jb * 64 + 63 > m0w);
#pragma unroll
            for (int nt = 0; nt < 8; nt++) {
#pragma unroll
                for (int e = 0; e < 4; e++) {
                    const int col_g = jb * 64 + nt * 8 + c0 + (e & 1);
                    const int row_g = m0w + r0 + ((e >> 1) << 3);
                    float p = fexp2(sfr[nt][e] * 0.1803368801f);
                    if (needmask && col_g > row_g) p = 0.0f;
                    sfr[nt][e] = p;
                    if (e < 2) l0 += p; else l1 += p;
                }
            }

            // ---- repack P -> fp16 A-frags ----
            uint32_t pa[4][4];
#pragma unroll
            for (int kk = 0; kk < 4; kk++) {
                const float* t0 = sfr[2 * kk];
                const float* t1 = sfr[2 * kk + 1];
                pa[kk][0] = packh(t0[0], t0[1]);
                pa[kk][1] = packh(t0[2], t0[3]);
                pa[kk][2] = packh(t1[0], t1[1]);
                pa[kk][3] = packh(t1[2], t1[3]);
            }

            // ---- O += P V (single fp16 term) ----
#pragma unroll
            for (int kk = 0; kk < 4; kk++) {
                const uint32_t kb = kk * 32 + lkh;
                uint32_t bv[8][2];
#pragma unroll
                for (int np = 0; np < 4; np++) {
                    const uint32_t off = swz((uint32_t)((np * 16 + lrow) * 128) + kb);
                    LDSM_X4(bv[2 * np][0], bv[2 * np + 1][0], bv[2 * np][1], bv[2 * np + 1][1],
                            sV + off);
                }
#pragma unroll
                for (int nt = 0; nt < 8; nt++)
                    MMA_F16(oacc[nt][0], oacc[nt][1], oacc[nt][2], oacc[nt][3],
                            pa[kk][0], pa[kk][1], pa[kk][2], pa[kk][3],
                            bv[nt][0], bv[nt][1]);
            }
        }
        __syncthreads();
    }

    l0 += __shfl_xor_sync(0xFFFFFFFF, l0, 1);
    l0 += __shfl_xor_sync(0xFFFFFFFF, l0, 2);
    l1 += __shfl_xor_sync(0xFFFFFFFF, l1, 1);
    l1 += __shfl_xor_sync(0xFFFFFFFF, l1, 2);
    const float inv0 = 1.0f / l0;
    const float inv1 = 1.0f / l1;

    const size_t row0 = (size_t)(b * T_ + m0w + r0);
#pragma unroll
    for (int nt = 0; nt < 8; nt++) {
        const int col = h * 64 + nt * 8 + c0;
        *(uint32_t*)(a16 + row0 * D_ + col) = packh(oacc[nt][0] * inv0, oacc[nt][1] * inv0);
        *(uint32_t*)(a16 + (row0 + 8) * D_ + col) = packh(oacc[nt][2] * inv1, oacc[nt][3] * inv1);
    }
}

// ---------------------------------------------------------------------------
// Inputs: 0 x, 1 mask, 2 Wq, 3 bq, 4 Wk, 5 Wv, 6 bv, 7 Wo, 8 bo
// ---------------------------------------------------------------------------
extern "C" void kernel_launch(void* const* d_in, const int* in_sizes, int n_in,
                              void* d_out, int out_size) {
    (void)in_sizes; (void)n_in; (void)out_size;
    const float* x  = (const float*)d_in[0];
    const float* Wq = (const float*)d_in[2];
    const float* bq = (const float*)d_in[3];
    const float* Wk = (const float*)d_in[4];
    const float* Wv = (const float*)d_in[5];
    const float* bv = (const float*)d_in[6];
    const float* Wo = (const float*)d_in[7];
    const float* bo = (const float*)d_in[8];
    float* out = (float*)d_out;

    __half *x16, *w16, *wo16, *a16, *q16, *k16, *v16, *vt16;
    cudaGetSymbolAddress((void**)&x16, g_x16);
    cudaGetSymbolAddress((void**)&w16, g_w16);
    cudaGetSymbolAddress((void**)&wo16, g_wo16);
    cudaGetSymbolAddress((void**)&a16, g_a16);
    cudaGetSymbolAddress((void**)&q16, g_q16);
    cudaGetSymbolAddress((void**)&k16, g_k16);
    cudaGetSymbolAddress((void**)&v16, g_v16);
    cudaGetSymbolAddress((void**)&vt16, g_vt16);

    cudaFuncSetAttribute(gemm16<0>, cudaFuncAttributeMaxDynamicSharedMemorySize, SM_GEMM);
    cudaFuncSetAttribute(gemm16<1>, cudaFuncAttributeMaxDynamicSharedMemorySize, SM_GEMM);
    cudaFuncSetAttribute(attn_mma, cudaFuncAttributeMaxDynamicSharedMemorySize, AT_SMEM);

    const int nx4 = NELT / 4;
    const int nw4 = (D_ * D_) / 4;
    cvt16<<<(nx4 + 255) / 256, 256>>>(x, x16, nx4);
    cvt16<<<(nw4 + 255) / 256, 256>>>(Wq, w16 + (size_t)0 * D_ * D_, nw4);
    cvt16<<<(nw4 + 255) / 256, 256>>>(Wk, w16 + (size_t)1 * D_ * D_, nw4);
    cvt16<<<(nw4 + 255) / 256, 256>>>(Wv, w16 + (size_t)2 * D_ * D_, nw4);
    cvt16<<<(nw4 + 255) / 256, 256>>>(Wo, wo16, nw4);

    dim3 qkvgrid(3 * D_ / 128, M_ / 128);   // (24, 64)
    gemm16<0><<<qkvgrid, 128, SM_GEMM>>>(x16, w16, bq, bv, nullptr,
                                         q16, k16, v16, nullptr);

    dim3 tgrid(T_ / 64, H_, B_);
    transp_v<<<tgrid, 128>>>(v16, vt16);

    dim3 agrid(T_ / 128, H_, B_);
    attn_mma<<<agrid, 256, AT_SMEM>>>(q16, k16, vt16, a16);

    dim3 ogrid(D_ / 128, M_ / 128);         // (8, 64)
    gemm16<1><<<ogrid, 128, SM_GEMM>>>(a16, wo16, nullptr, nullptr, bo,
                                       nullptr, nullptr, nullptr, out);
}

// round 12
// speedup vs baseline: 5.7020x; 1.0688x over previous
#include <cuda_runtime.h>
#include <cuda_fp16.h>
#include <cstdint>

#define B_ 8
#define T_ 1024
#define D_ 1024
#define H_ 16
#define HD 64
#define M_ (B_ * T_)     // 8192
#define NELT (M_ * D_)   // 8388608
#define NIT16 (D_ / 64)  // 16 k-iters (K=1024, BK=64)

// ---------------- scratch (static __device__; no cudaMalloc allowed) --------
__device__ __align__(256) __half g_x16[NELT];
__device__ __align__(256) __half g_w16[(size_t)3 * D_ * D_];   // [Wq;Wk;Wv]
__device__ __align__(256) __half g_wo16[(size_t)D_ * D_];
__device__ __align__(256) __half g_a16[NELT];

__device__ __align__(256) __half g_q16[NELT];
__device__ __align__(256) __half g_k16[NELT];
__device__ __align__(256) __half g_v16[NELT];

// ---------------- helpers ---------------------------------------------------
__device__ __forceinline__ uint32_t smem_u32(const void* p) {
    uint32_t a;
    asm("{ .reg .u64 t; cvta.to.shared.u64 t, %1; cvt.u32.u64 %0, t; }" : "=r"(a) : "l"(p));
    return a;
}
__device__ __forceinline__ uint32_t swz(uint32_t off) { return off ^ ((off >> 3) & 0x70); }

#define CP_ASYNC16(dst, src) \
    asm volatile("cp.async.cg.shared.global [%0], [%1], 16;" :: "r"(dst), "l"(src))
#define CP_COMMIT()  asm volatile("cp.async.commit_group;" ::: "memory")
#define CP_WAIT1()   asm volatile("cp.async.wait_group 1;" ::: "memory")

#define LDSM_X4(r0, r1, r2, r3, addr) \
    asm volatile("ldmatrix.sync.aligned.m8n8.x4.shared.b16 {%0,%1,%2,%3}, [%4];" \
        : "=r"(r0), "=r"(r1), "=r"(r2), "=r"(r3) : "r"(addr))

#define LDSM_X4_T(r0, r1, r2, r3, addr) \
    asm volatile("ldmatrix.sync.aligned.m8n8.x4.trans.shared.b16 {%0,%1,%2,%3}, [%4];" \
        : "=r"(r0), "=r"(r1), "=r"(r2), "=r"(r3) : "r"(addr))

#define MMA_F16(c0, c1, c2, c3, a0, a1, a2, a3, b0, b1) \
    asm volatile("mma.sync.aligned.m16n8k16.row.col.f32.f16.f16.f32 " \
        "{%0,%1,%2,%3}, {%4,%5,%6,%7}, {%8,%9}, {%0,%1,%2,%3};" \
        : "+f"(c0), "+f"(c1), "+f"(c2), "+f"(c3) \
        : "r"(a0), "r"(a1), "r"(a2), "r"(a3), "r"(b0), "r"(b1))

__device__ __forceinline__ uint32_t packh(float lo, float hi) {
    __half2 h = __floats2half2_rn(lo, hi);
    return *(uint32_t*)&h;
}

__device__ __forceinline__ float fexp2(float y) {
    y = fmaxf(y, -126.0f);
    float t = y + 12582912.0f;
    int i = __float_as_int(t) - 0x4B400000;
    float f = y - (t - 12582912.0f);
    float p = 0.001333356f;
    p = fmaf(p, f, 0.009618129f);
    p = fmaf(p, f, 0.05550411f);
    p = fmaf(p, f, 0.2402265f);
    p = fmaf(p, f, 0.6931472f);
    p = fmaf(p, f, 1.0f);
    return p * __int_as_float((i + 127) << 23);
}

// ---------------- fused fp32 -> fp16 convert (x + Wq + Wk + Wv + Wo) ---------
#define XF4  (NELT / 4)             // 2097152
#define WF4  ((D_ * D_) / 4)        // 262144
#define TOTF4 (XF4 + 4 * WF4)       // 3145728

__global__ void cvt_all(const float* __restrict__ x,
                        const float* __restrict__ wq, const float* __restrict__ wk,
                        const float* __restrict__ wv, const float* __restrict__ wo,
                        __half* __restrict__ x16, __half* __restrict__ w16,
                        __half* __restrict__ wo16) {
    int i = blockIdx.x * blockDim.x + threadIdx.x;
    if (i >= TOTF4) return;
    const float* s;
    __half* d;
    int off;
    if (i < XF4) { s = x; d = x16; off = i; }
    else if (i < XF4 + WF4)     { s = wq; d = w16;                       off = i - XF4; }
    else if (i < XF4 + 2 * WF4) { s = wk; d = w16 + (size_t)D_ * D_;     off = i - XF4 - WF4; }
    else if (i < XF4 + 3 * WF4) { s = wv; d = w16 + (size_t)2 * D_ * D_; off = i - XF4 - 2 * WF4; }
    else                        { s = wo; d = wo16;                      off = i - XF4 - 3 * WF4; }
    float4 v = ((const float4*)s)[off];
    ((__half2*)d)[2 * off + 0] = __floats2half2_rn(v.x, v.y);
    ((__half2*)d)[2 * off + 1] = __floats2half2_rn(v.z, v.w);
}

// ---------------- fp16 HMMA GEMM (K=1024) ------------------------------------
// 128 threads, 4 warps 64x64, CTA 128x128, 3-stage cp.async, 2 CTA/SM.
#define STAGE_B 32768
#define SM_GEMM (3 * STAGE_B)

template <int MODE>
__global__ __launch_bounds__(128, 2)
void gemm16(const __half* __restrict__ A2, const __half* __restrict__ B2,
            const float* __restrict__ bq, const float* __restrict__ bvv,
            const float* __restrict__ bo,
            __half* __restrict__ q16, __half* __restrict__ k16,
            __half* __restrict__ v16, float* __restrict__ C) {
    extern __shared__ char smem[];
    const uint32_t sbase = smem_u32(smem);
    const int tid = threadIdx.x;
    const int wid = tid >> 5;
    const int lane = tid & 31;
    const int m0 = blockIdx.y * 128;
    const int n0 = blockIdx.x * 128;

    const int r_ld = tid >> 3;
    const int c_ld = tid & 7;

    const __half* Abase = A2 + (size_t)(m0 + r_ld * 8) * D_ + c_ld * 8;
    const __half* Bbase = B2 + (size_t)(n0 + r_ld * 8) * D_ + c_ld * 8;

    float acc[4][8][4];
#pragma unroll
    for (int i = 0; i < 4; i++)
#pragma unroll
        for (int j = 0; j < 8; j++)
#pragma unroll
            for (int t = 0; t < 4; t++) acc[i][j][t] = 0.0f;

    auto load_stage = [&](int stage, int kt) {
        const uint32_t sA = sbase + stage * STAGE_B;
        const uint32_t sB = sA + 16384;
        const size_t koff = (size_t)kt * 64;
#pragma unroll
        for (int j = 0; j < 8; j++) {
            const int r = r_ld * 8 + j;
            CP_ASYNC16(sA + swz((uint32_t)(r * 128 + c_ld * 16)),
                       Abase + (size_t)j * D_ + koff);
        }
#pragma unroll
        for (int j = 0; j < 8; j++) {
            const int r = r_ld * 8 + j;
            CP_ASYNC16(sB + swz((uint32_t)(r * 128 + c_ld * 16)),
                       Bbase + (size_t)j * D_ + koff);
        }
    };

    load_stage(0, 0); CP_COMMIT();
    load_stage(1, 1); CP_COMMIT();

    const int wm = (wid & 1) * 64;
    const int wn = (wid >> 1) * 64;
    const int lrow = lane & 15;
    const int lkhalf = ((lane >> 4) & 1) * 16;

    for (int kt = 0; kt < NIT16; kt++) {
        CP_WAIT1();
        __syncthreads();
        if (kt + 2 < NIT16) load_stage((kt + 2) % 3, kt + 2);
        CP_COMMIT();

        const uint32_t sA = sbase + (kt % 3) * STAGE_B;
        const uint32_t sB = sA + 16384;

#pragma unroll
        for (int k16 = 0; k16 < 4; k16++) {
            const uint32_t kb = k16 * 32 + lkhalf;
            uint32_t a[4][4], b[8][2];
#pragma unroll
            for (int mt = 0; mt < 4; mt++) {
                const uint32_t ad = sA + swz((uint32_t)((wm + mt * 16 + lrow) * 128) + kb);
                LDSM_X4(a[mt][0], a[mt][1], a[mt][2], a[mt][3], ad);
            }
#pragma unroll
            for (int np = 0; np < 4; np++) {
                const uint32_t bd = sB + swz((uint32_t)((wn + np * 16 + lrow) * 128) + kb);
                LDSM_X4(b[2 * np][0], b[2 * np + 1][0], b[2 * np][1], b[2 * np + 1][1], bd);
            }
#pragma unroll
            for (int mt = 0; mt < 4; mt++)
#pragma unroll
                for (int nt = 0; nt < 8; nt++)
                    MMA_F16(acc[mt][nt][0], acc[mt][nt][1], acc[mt][nt][2], acc[mt][nt][3],
                            a[mt][0], a[mt][1], a[mt][2], a[mt][3],
                            b[nt][0], b[nt][1]);
        }
    }

    // ---- epilogue ----
    const int em = m0 + wm + (lane >> 2);
    const int region = n0 >> 10;
    const int nbase = (MODE == 0 ? (n0 & 1023) : n0) + wn + (lane & 3) * 2;

    const float* bias = (MODE == 1) ? bo : (region == 0 ? bq : (region == 2 ? bvv : nullptr));
    __half* Dst = nullptr;
    if (MODE == 0) Dst = (region == 0 ? q16 : (region == 1 ? k16 : v16));

#pragma unroll
    for (int mt = 0; mt < 4; mt++) {
#pragma unroll
        for (int nt = 0; nt < 8; nt++) {
            const int n = nbase + nt * 8;
            float2 bb = make_float2(0.f, 0.f);
            if (bias) bb = *(const float2*)(bias + n);
            float v0 = acc[mt][nt][0] + bb.x, v1 = acc[mt][nt][1] + bb.y;
            float v2 = acc[mt][nt][2] + bb.x, v3 = acc[mt][nt][3] + bb.y;
            const size_t r0 = (size_t)(em + mt * 16) * D_ + n;
            const size_t r1 = (size_t)(em + mt * 16 + 8) * D_ + n;
            if (MODE == 0) {
                *(uint32_t*)(Dst + r0) = packh(v0, v1);
                *(uint32_t*)(Dst + r1) = packh(v2, v3);
            } else {
                *(float2*)(C + r0) = make_float2(v0, v1);
                *(float2*)(C + r1) = make_float2(v2, v3);
            }
        }
    }
}

// ---------------- single-term fp16 causal flash attention --------------------
// CTA: 128 q-rows x (b,h). 8 warps x 16 rows. Q 16KB + 3 stages x {K 8KB, V 8KB}.
// V is staged in K-layout ([token][d]); P*V B-fragments via ldmatrix.trans.
#define AT_SQ    16384
#define AT_STAGE 16384
#define AT_SMEM  (AT_SQ + 3 * AT_STAGE)    // 65536

__global__ __launch_bounds__(256, 2)
void attn_mma(const __half* __restrict__ q16, const __half* __restrict__ k16,
              const __half* __restrict__ v16, __half* __restrict__ a16) {
    extern __shared__ char smem[];
    const uint32_t sbase = smem_u32(smem);
    const int tid = threadIdx.x;
    const int wid = tid >> 5;
    const int lane = tid & 31;
    const int iq = blockIdx.x;
    const int h  = blockIdx.y;
    const int b  = blockIdx.z;
    const int nblocks = 2 * iq + 2;

    // stage Q
#pragma unroll
    for (int it = 0; it < 4; it++) {
        const int idx = it * 256 + tid;
        const int r = idx >> 3, c = idx & 7;
        CP_ASYNC16(sbase + swz((uint32_t)(r * 128 + c * 16)),
                   q16 + (size_t)(b * T_ + iq * 128 + r) * D_ + h * 64 + c * 8);
    }
    auto pf_kv = [&](int jb) {
        const uint32_t s0 = sbase + AT_SQ + (jb % 3) * AT_STAGE;
#pragma unroll
        for (int it = 0; it < 2; it++) {
            const int idx = it * 256 + tid;
            const int r = idx >> 3, c = idx & 7;
            const size_t gb = (size_t)(b * T_ + jb * 64 + r) * D_ + h * 64 + c * 8;
            CP_ASYNC16(s0 + swz((uint32_t)(r * 128 + c * 16)), k16 + gb);
            CP_ASYNC16(s0 + 8192 + swz((uint32_t)(r * 128 + c * 16)), v16 + gb);
        }
    };

    pf_kv(0); CP_COMMIT();
    if (nblocks > 1) pf_kv(1);
    CP_COMMIT();

    float oacc[8][4];
#pragma unroll
    for (int i = 0; i < 8; i++)
#pragma unroll
        for (int j = 0; j < 4; j++) oacc[i][j] = 0.0f;
    float l0 = 0.0f, l1 = 0.0f;

    const int m0w = iq * 128 + wid * 16;
    const int r0 = lane >> 2;
    const int c0 = (lane & 3) * 2;
    const int lrow = lane & 15;
    const int lkh = ((lane >> 4) & 1) * 16;
    // V trans-load lane addressing: row = t (k dim), col-byte = d segment
    const int vrow_l = (lane & 7) + ((lane >> 4) & 1) * 8;
    const uint32_t vcol_l = ((lane >> 3) & 1) * 16;

    for (int jb = 0; jb < nblocks; jb++) {
        CP_WAIT1();
        __syncthreads();
        if (jb + 2 < nblocks) pf_kv(jb + 2);
        CP_COMMIT();

        const uint32_t sK = sbase + AT_SQ + (jb % 3) * AT_STAGE;
        const uint32_t sV = sK + 8192;

        if (jb * 64 <= m0w + 15) {
            float sfr[8][4];
#pragma unroll
            for (int i = 0; i < 8; i++)
#pragma unroll
                for (int j = 0; j < 4; j++) sfr[i][j] = 0.0f;

            // ---- S = Q K^T ----
#pragma unroll
            for (int k16i = 0; k16i < 4; k16i++) {
                const uint32_t kb = k16i * 32 + lkh;
                uint32_t a[4], bk[8][2];
                LDSM_X4(a[0], a[1], a[2], a[3],
                        sbase + swz((uint32_t)((wid * 16 + lrow) * 128) + kb));
#pragma unroll
                for (int np = 0; np < 4; np++) {
                    const uint32_t off = swz((uint32_t)((np * 16 + lrow) * 128) + kb);
                    LDSM_X4(bk[2 * np][0], bk[2 * np + 1][0], bk[2 * np][1], bk[2 * np + 1][1],
                            sK + off);
                }
#pragma unroll
                for (int nt = 0; nt < 8; nt++)
                    MMA_F16(sfr[nt][0], sfr[nt][1], sfr[nt][2], sfr[nt][3],
                            a[0], a[1], a[2], a[3], bk[nt][0], bk[nt][1]);
            }

            // ---- p = exp(s/8), causal mask, row sums ----
            const bool needmask = (jb * 64 + 63 > m0w);
#pragma unroll
            for (int nt = 0; nt < 8; nt++) {
#pragma unroll
                for (int e = 0; e < 4; e++) {
                    const int col_g = jb * 64 + nt * 8 + c0 + (e & 1);
                    const int row_g = m0w + r0 + ((e >> 1) << 3);
                    float p = fexp2(sfr[nt][e] * 0.1803368801f);
                    if (needmask && col_g > row_g) p = 0.0f;
                    sfr[nt][e] = p;
                    if (e < 2) l0 += p; else l1 += p;
                }
            }

            // ---- repack P -> fp16 A-frags ----
            uint32_t pa[4][4];
#pragma unroll
            for (int kk = 0; kk < 4; kk++) {
                const float* t0 = sfr[2 * kk];
                const float* t1 = sfr[2 * kk + 1];
                pa[kk][0] = packh(t0[0], t0[1]);
                pa[kk][1] = packh(t0[2], t0[3]);
                pa[kk][2] = packh(t1[0], t1[1]);
                pa[kk][3] = packh(t1[2], t1[3]);
            }

            // ---- O += P V : B-frags via ldmatrix.trans on K-layout V tile ----
#pragma unroll
            for (int kk = 0; kk < 4; kk++) {
                uint32_t bv[8][2];
                const uint32_t vrow = (uint32_t)(kk * 16 + vrow_l) * 128;
#pragma unroll
                for (int np = 0; np < 4; np++) {
                    const uint32_t off = swz(vrow + np * 32 + vcol_l);
                    LDSM_X4_T(bv[2 * np][0], bv[2 * np + 1][0], bv[2 * np][1], bv[2 * np + 1][1],
                              sV + off);
                }
#pragma unroll
                for (int nt = 0; nt < 8; nt++)
                    MMA_F16(oacc[nt][0], oacc[nt][1], oacc[nt][2], oacc[nt][3],
                            pa[kk][0], pa[kk][1], pa[kk][2], pa[kk][3],
                            bv[nt][0], bv[nt][1]);
            }
        }
        __syncthreads();
    }

    l0 += __shfl_xor_sync(0xFFFFFFFF, l0, 1);
    l0 += __shfl_xor_sync(0xFFFFFFFF, l0, 2);
    l1 += __shfl_xor_sync(0xFFFFFFFF, l1, 1);
    l1 += __shfl_xor_sync(0xFFFFFFFF, l1, 2);
    const float inv0 = 1.0f / l0;
    const float inv1 = 1.0f / l1;

    const size_t row0 = (size_t)(b * T_ + m0w + r0);
#pragma unroll
    for (int nt = 0; nt < 8; nt++) {
        const int col = h * 64 + nt * 8 + c0;
        *(uint32_t*)(a16 + row0 * D_ + col) = packh(oacc[nt][0] * inv0, oacc[nt][1] * inv0);
        *(uint32_t*)(a16 + (row0 + 8) * D_ + col) = packh(oacc[nt][2] * inv1, oacc[nt][3] * inv1);
    }
}

// ---------------------------------------------------------------------------
// Inputs: 0 x, 1 mask, 2 Wq, 3 bq, 4 Wk, 5 Wv, 6 bv, 7 Wo, 8 bo
// ---------------------------------------------------------------------------
extern "C" void kernel_launch(void* const* d_in, const int* in_sizes, int n_in,
                              void* d_out, int out_size) {
    (void)in_sizes; (void)n_in; (void)out_size;
    const float* x  = (const float*)d_in[0];
    const float* Wq = (const float*)d_in[2];
    const float* bq = (const float*)d_in[3];
    const float* Wk = (const float*)d_in[4];
    const float* Wv = (const float*)d_in[5];
    const float* bv = (const float*)d_in[6];
    const float* Wo = (const float*)d_in[7];
    const float* bo = (const float*)d_in[8];
    float* out = (float*)d_out;

    __half *x16, *w16, *wo16, *a16, *q16, *k16, *v16;
    cudaGetSymbolAddress((void**)&x16, g_x16);
    cudaGetSymbolAddress((void**)&w16, g_w16);
    cudaGetSymbolAddress((void**)&wo16, g_wo16);
    cudaGetSymbolAddress((void**)&a16, g_a16);
    cudaGetSymbolAddress((void**)&q16, g_q16);
    cudaGetSymbolAddress((void**)&k16, g_k16);
    cudaGetSymbolAddress((void**)&v16, g_v16);

    cudaFuncSetAttribute(gemm16<0>, cudaFuncAttributeMaxDynamicSharedMemorySize, SM_GEMM);
    cudaFuncSetAttribute(gemm16<1>, cudaFuncAttributeMaxDynamicSharedMemorySize, SM_GEMM);
    cudaFuncSetAttribute(attn_mma, cudaFuncAttributeMaxDynamicSharedMemorySize, AT_SMEM);

    cvt_all<<<(TOTF4 + 255) / 256, 256>>>(x, Wq, Wk, Wv, Wo, x16, w16, wo16);

    dim3 qkvgrid(3 * D_ / 128, M_ / 128);   // (24, 64)
    gemm16<0><<<qkvgrid, 128, SM_GEMM>>>(x16, w16, bq, bv, nullptr,
                                         q16, k16, v16, nullptr);

    dim3 agrid(T_ / 128, H_, B_);
    attn_mma<<<agrid, 256, AT_SMEM>>>(q16, k16, v16, a16);

    dim3 ogrid(D_ / 128, M_ / 128);         // (8, 64)
    gemm16<1><<<ogrid, 128, SM_GEMM>>>(a16, wo16, nullptr, nullptr, bo,
                                       nullptr, nullptr, nullptr, out);
}